// round 13
// baseline (speedup 1.0000x reference)
#include <cuda_runtime.h>
#include <cuda_bf16.h>
#include <math.h>
#include <stdint.h>

#define NN      50048      // padded node count (391 * 128)
#define NREAL   50000
#define NE      300000
#define KD      256
#define HID     256
#define NSTEP   8
#define SCANB   ((NN + 1023) / 1024)   // 49

// ---------------- scratch (static device globals; no runtime alloc) ----------
__device__ float g_h [NN * HID];
__device__ __nv_bfloat16 g_hHa[NN * KD], g_hLa[NN * KD];
__device__ __nv_bfloat16 g_hHb[NN * KD], g_hLb[NN * KD];
__device__ __nv_bfloat16 g_xH[NN * KD],  g_xL[NN * KD];
__device__ __nv_bfloat16 g_aggH[NN * KD], g_aggL[NN * KD];
__device__ __nv_bfloat16 g_WloH[NSTEP * 768 * 256], g_WloL[NSTEP * 768 * 256];
__device__ __nv_bfloat16 g_WhiH[768 * 256], g_WhiL[768 * 256];
__device__ __nv_bfloat16 g_WredH[256 * KD], g_WredL[256 * KD];
__device__ __nv_bfloat16 g_WihH[768 * KD], g_WihL[768 * KD];
__device__ __nv_bfloat16 g_WgH[NSTEP * 256 * 256], g_WgL[NSTEP * 256 * 256];
__device__ float g_cb4[1024];
__device__ int g_cnt[NN], g_rowptr[NN + 1], g_cur[NN], g_eidx[NE];
__device__ int g_bsum[SCANB], g_boff[SCANB];

// ---------------- shared GEMM machinery --------------------------------------
#define BK    32
#define SA    40                       // smem row stride in bf16 elems (80B)
#define PLANEB (128 * SA * 2)          // 10240 B
#define STAGEB (4 * PLANEB)            // 40960 B (init/wfus stage)
#define GSMEM  (2 * STAGEB)            // 81920 B
#define BCPL   (96 * SA * 2)           // 7680 B compact B plane
#define STGF   (2 * PLANEB + 2 * BCPL) // 35840 B fused stage
#define GSMEMF (2 * STGF)              // 71680 B

__device__ __forceinline__ void mma_bf16(float* c, const unsigned* a, const unsigned* b)
{
    asm volatile(
        "mma.sync.aligned.m16n8k16.row.col.f32.bf16.bf16.f32 "
        "{%0,%1,%2,%3}, {%4,%5,%6,%7}, {%8,%9}, {%0,%1,%2,%3};\n"
        : "+f"(c[0]), "+f"(c[1]), "+f"(c[2]), "+f"(c[3])
        : "r"(a[0]), "r"(a[1]), "r"(a[2]), "r"(a[3]), "r"(b[0]), "r"(b[1]));
}
__device__ __forceinline__ void ldsm4(unsigned* r, uint32_t addr)
{
    asm volatile("ldmatrix.sync.aligned.m8n8.x4.shared.b16 {%0,%1,%2,%3}, [%4];"
                 : "=r"(r[0]), "=r"(r[1]), "=r"(r[2]), "=r"(r[3]) : "r"(addr));
}
__device__ __forceinline__ void cpasync16(char* dst, const void* src)
{
    asm volatile("cp.async.cg.shared.global [%0], [%1], 16;"
                 :: "l"((uint64_t)__cvta_generic_to_shared(dst)), "l"(src) : "memory");
}

#define GEMM_COMPUTE(base, BHOFF, BLOFF)                                       \
    do {                                                                       \
        _Pragma("unroll")                                                      \
        for (int ks = 0; ks < 2; ks++) {                                       \
            const uint32_t kso = ks * 32;                                      \
            unsigned aH[2][4], aL[2][4];                                       \
            ldsm4(aH[0], (base) + 0 * PLANEB + aoffH0 + kso);                  \
            ldsm4(aH[1], (base) + 0 * PLANEB + aoffH1 + kso);                  \
            ldsm4(aL[0], (base) + 1 * PLANEB + aoffH0 + kso);                  \
            ldsm4(aL[1], (base) + 1 * PLANEB + aoffH1 + kso);                  \
            _Pragma("unroll")                                                  \
            for (int ni2 = 0; ni2 < 8; ni2 += 2) {                             \
                unsigned bH[4], bL[4];                                         \
                const uint32_t bo = boff0 + (uint32_t)(ni2 * 8 * SA * 2) + kso;\
                ldsm4(bH, (base) + (BHOFF) + bo);                              \
                ldsm4(bL, (base) + (BLOFF) + bo);                              \
                _Pragma("unroll")                                              \
                for (int mi = 0; mi < 2; mi++)                                 \
                    _Pragma("unroll")                                          \
                    for (int q = 0; q < 2; q++)                                \
                        mma_bf16(acc[mi][ni2 + q], aH[mi], bH + q * 2);        \
                _Pragma("unroll")                                              \
                for (int mi = 0; mi < 2; mi++)                                 \
                    _Pragma("unroll")                                          \
                    for (int q = 0; q < 2; q++)                                \
                        mma_bf16(acc[mi][ni2 + q], aH[mi], bL + q * 2);        \
                _Pragma("unroll")                                              \
                for (int mi = 0; mi < 2; mi++)                                 \
                    _Pragma("unroll")                                          \
                    for (int q = 0; q < 2; q++)                                \
                        mma_bf16(acc[mi][ni2 + q], aL[mi], bH + q * 2);        \
            }                                                                  \
        }                                                                      \
    } while (0)

#define FRAG_SETUP()                                                           \
    const int tid  = threadIdx.x;                                              \
    const int lane = tid & 31;                                                 \
    const int warp = tid >> 5;                                                 \
    const int wm   = warp & 3;                                                 \
    const int wn   = warp >> 2;                                                \
    const int g    = lane >> 2;                                                \
    const int tq   = lane & 3;                                                 \
    const int a_row = wm * 32 + (lane & 15);                                   \
    const int a_kx  = (lane >> 4) * 16;                                        \
    const uint32_t aoffH0 = (uint32_t)(a_row * SA * 2 + a_kx);                 \
    const uint32_t aoffH1 = aoffH0 + 16 * SA * 2;                              \
    const int b_col = wn * 64 + (lane & 7) + ((lane >> 4) & 1) * 8;            \
    const int b_kx  = ((lane >> 3) & 1) * 16;                                  \
    const uint32_t boff0 = (uint32_t)(b_col * SA * 2 + b_kx)

#define ACC_INIT()                                                             \
    float acc[2][8][4];                                                        \
    _Pragma("unroll")                                                          \
    for (int mi = 0; mi < 2; mi++)                                             \
        _Pragma("unroll")                                                      \
        for (int ni = 0; ni < 8; ni++)                                         \
            _Pragma("unroll")                                                  \
            for (int j = 0; j < 4; j++) acc[mi][ni][j] = 0.0f

__device__ __forceinline__ void split1(float v, __nv_bfloat16& h, __nv_bfloat16& l) {
    h = __float2bfloat16(v);
    l = __float2bfloat16(v - __bfloat162float(h));
}
__device__ __forceinline__ float sigf(float x) { return 1.0f / (1.0f + __expf(-x)); }

// ---------------- init GEMM: C = A@B^T + bias --------------------------------
__global__ void __launch_bounds__(256, 2)
gemm_init(const __nv_bfloat16* __restrict__ AH, const __nv_bfloat16* __restrict__ AL,
          const __nv_bfloat16* __restrict__ BH, const __nv_bfloat16* __restrict__ BL,
          const float* __restrict__ bias, float* __restrict__ C, int ldc)
{
    extern __shared__ char sm[];
    const uint32_t sb = (uint32_t)__cvta_generic_to_shared(sm);
    FRAG_SETUP();
    const int row0 = blockIdx.y * 128, col0 = blockIdx.x * 128;
    const __nv_bfloat16* gp[4] = {AH, AL, BH, BL};

    auto copy_stage = [&](int st, int kc) {
        const int k0 = kc * BK;
        char* dst0 = sm + st * STAGEB;
#pragma unroll
        for (int i = 0; i < 8; i++) {
            const int idx = i * 256 + tid;
            const int p = idx >> 9, r = (idx >> 2) & 127, j = idx & 3;
            const int grow = ((p < 2) ? row0 : col0) + r;
            cpasync16(dst0 + p * PLANEB + r * (SA * 2) + j * 16,
                      gp[p] + (size_t)grow * KD + k0 + j * 8);
        }
        asm volatile("cp.async.commit_group;" ::: "memory");
    };

    ACC_INIT();
    copy_stage(0, 0);
    const int NCHUNK = KD / BK;
    for (int c = 0; c < NCHUNK; c++) {
        asm volatile("cp.async.wait_group 0;" ::: "memory");
        __syncthreads();
        if (c + 1 < NCHUNK) copy_stage((c + 1) & 1, c + 1);
        GEMM_COMPUTE(sb + (c & 1) * STAGEB, 2 * PLANEB, 3 * PLANEB);
    }
#pragma unroll
    for (int mi = 0; mi < 2; mi++) {
        const int r = row0 + wm * 32 + mi * 16 + g;
#pragma unroll
        for (int ni = 0; ni < 8; ni++) {
            const int cc = col0 + wn * 64 + ni * 8 + tq * 2;
            const float b0 = bias[cc], b1 = bias[cc + 1];
            *(float2*)(C + (size_t)r * ldc + cc) =
                make_float2(acc[mi][ni][0] + b0, acc[mi][ni][1] + b1);
            *(float2*)(C + (size_t)(r + 8) * ldc + cc) =
                make_float2(acc[mi][ni][2] + b0, acc[mi][ni][3] + b1);
        }
    }
}

// ---------------- Wfused GEMM -> compact-lo layout ---------------------------
// Wfus[t][o=gate*256+hid][k] = sum_c Wih[o][c] * Wg_t[k][c]; written at
// rcomp = (hid>>5)*96 + ((hid>>4)&1)*48 + gate*16 + (hid&15).
__global__ void __launch_bounds__(256, 2)
gemm_wfus(const __nv_bfloat16* __restrict__ AH, const __nv_bfloat16* __restrict__ AL,
          const __nv_bfloat16* __restrict__ BHall, const __nv_bfloat16* __restrict__ BLall,
          __nv_bfloat16* __restrict__ loH, __nv_bfloat16* __restrict__ loL)
{
    extern __shared__ char sm[];
    const uint32_t sb = (uint32_t)__cvta_generic_to_shared(sm);
    FRAG_SETUP();
    const int row0 = blockIdx.y * 128, col0 = blockIdx.x * 128;
    const int t = blockIdx.z;
    const __nv_bfloat16* gp[4] = {AH, AL, BHall + (size_t)t * 65536,
                                  BLall + (size_t)t * 65536};

    auto copy_stage = [&](int st, int kc) {
        const int k0 = kc * BK;
        char* dst0 = sm + st * STAGEB;
#pragma unroll
        for (int i = 0; i < 8; i++) {
            const int idx = i * 256 + tid;
            const int p = idx >> 9, r = (idx >> 2) & 127, j = idx & 3;
            const int grow = ((p < 2) ? row0 : col0) + r;
            cpasync16(dst0 + p * PLANEB + r * (SA * 2) + j * 16,
                      gp[p] + (size_t)grow * 256 + k0 + j * 8);
        }
        asm volatile("cp.async.commit_group;" ::: "memory");
    };

    ACC_INIT();
    copy_stage(0, 0);
    for (int c = 0; c < 8; c++) {
        asm volatile("cp.async.wait_group 0;" ::: "memory");
        __syncthreads();
        if (c + 1 < 8) copy_stage((c + 1) & 1, c + 1);
        GEMM_COMPUTE(sb + (c & 1) * STAGEB, 2 * PLANEB, 3 * PLANEB);
    }
    const size_t tb = (size_t)t * 768 * 256;
#pragma unroll
    for (int mi = 0; mi < 2; mi++) {
        const int r = row0 + wm * 32 + mi * 16 + g;
#pragma unroll
        for (int ni = 0; ni < 8; ni++) {
            const int cc = col0 + wn * 64 + ni * 8 + tq * 2;
#pragma unroll
            for (int j = 0; j < 4; j++) {
                const int o  = (j < 2) ? r : r + 8;
                const int kk = cc + (j & 1);
                const int gate = o >> 8, hid = o & 255;
                const int R = (hid >> 5) * 96 + ((hid >> 4) & 1) * 48
                            + gate * 16 + (hid & 15);
                __nv_bfloat16 hv, lv;
                split1(acc[mi][ni][j], hv, lv);
                loH[tb + (size_t)R * 256 + kk] = hv;
                loL[tb + (size_t)R * 256 + kk] = lv;
            }
        }
    }
}

// ---------------- fused step GEMM + GRU (128x128 tile, compact B) ------------
// grid (8, NN/128), 256 thr, 2-stage. Virtual cols per warp: [r16|z16|i16|n16].
__global__ void __launch_bounds__(256, 2)
gemm_gru(const __nv_bfloat16* __restrict__ aggH, const __nv_bfloat16* __restrict__ aggL,
         const __nv_bfloat16* __restrict__ hInH, const __nv_bfloat16* __restrict__ hInL,
         const __nv_bfloat16* __restrict__ WloH, const __nv_bfloat16* __restrict__ WloL,
         const __nv_bfloat16* __restrict__ WhiH, const __nv_bfloat16* __restrict__ WhiL,
         const float* __restrict__ cb4, float* __restrict__ h,
         __nv_bfloat16* __restrict__ outH, __nv_bfloat16* __restrict__ outL)
{
    extern __shared__ char sm[];
    const uint32_t sb = (uint32_t)__cvta_generic_to_shared(sm);
    const int tid  = threadIdx.x;
    const int lane = tid & 31;
    const int warp = tid >> 5;
    const int wm   = warp & 3;          // 4 wm x 2 wn
    const int wn   = warp >> 2;
    const int g    = lane >> 2;
    const int tq   = lane & 3;
    const int a_row = wm * 32 + (lane & 15);
    const int a_kx  = (lane >> 4) * 16;
    const uint32_t aoffH0 = (uint32_t)(a_row * SA * 2 + a_kx);
    const uint32_t aoffH1 = aoffH0 + 16 * SA * 2;
    // compact B col for slot s: wn*48 + s*16 + (lane&7) + ((lane>>4)&1)*8
    const uint32_t boffc0 = (uint32_t)((wn * 48 + (lane & 7) + ((lane >> 4) & 1) * 8)
                                       * (SA * 2) + ((lane >> 3) & 1) * 16);
    const int row0 = blockIdx.y * 128;
    const int bx   = blockIdx.x;

    auto copy_stage = [&](int st, int kc) {
        const bool klo = kc < 8;
        const int ka = klo ? kc * 32 : kc * 32 - 256;
        const __nv_bfloat16* a0 = klo ? aggH : hInH;
        const __nv_bfloat16* a1 = klo ? aggL : hInL;
        const __nv_bfloat16* w0 = klo ? WloH : WhiH;
        const __nv_bfloat16* w1 = klo ? WloL : WhiL;
        char* d = sm + st * STGF;
#pragma unroll
        for (int i = 0; i < 7; i++) {
            const int idx = i * 256 + tid;            // 0..1791
            if (idx < 1024) {
                const int p = idx >> 9, r = (idx >> 2) & 127, j = idx & 3;
                cpasync16(d + p * PLANEB + r * (SA * 2) + j * 16,
                          (p ? a1 : a0) + (size_t)(row0 + r) * KD + ka + j * 8);
            } else {
                const int rb = idx - 1024;            // 0..767
                const int p = rb >= 384 ? 1 : 0;
                const int rr = p ? rb - 384 : rb;
                const int r = rr >> 2, j = rr & 3;    // r 0..95
                cpasync16(d + 2 * PLANEB + p * BCPL + r * (SA * 2) + j * 16,
                          (p ? w1 : w0) + (size_t)(bx * 96 + r) * 256 + ka + j * 8);
            }
        }
        asm volatile("cp.async.commit_group;" ::: "memory");
    };

    ACC_INIT();
    copy_stage(0, 0);
    for (int c = 0; c < 16; c++) {
        asm volatile("cp.async.wait_group 0;" ::: "memory");
        __syncthreads();
        if (c + 1 < 16) copy_stage((c + 1) & 1, c + 1);
        const uint32_t base = sb + (uint32_t)((c & 1) * STGF);
        const bool klo = c < 8;
#pragma unroll
        for (int ks = 0; ks < 2; ks++) {
            const uint32_t kso = ks * 32;
            unsigned aH[2][4], aL[2][4];
            ldsm4(aH[0], base + 0 * PLANEB + aoffH0 + kso);
            ldsm4(aH[1], base + 0 * PLANEB + aoffH1 + kso);
            ldsm4(aL[0], base + 1 * PLANEB + aoffH0 + kso);
            ldsm4(aL[1], base + 1 * PLANEB + aoffH1 + kso);
#pragma unroll
            for (int s = 0; s < 3; s++) {
                const int ni2 = (s == 2) ? (klo ? 4 : 6) : 2 * s;
                unsigned bH[4], bL[4];
                const uint32_t bo = boffc0 + (uint32_t)(s * 16 * SA * 2) + kso;
                ldsm4(bH, base + 2 * PLANEB + bo);
                ldsm4(bL, base + 2 * PLANEB + BCPL + bo);
#pragma unroll
                for (int mi = 0; mi < 2; mi++)
#pragma unroll
                    for (int q = 0; q < 2; q++)
                        mma_bf16(acc[mi][ni2 + q], aH[mi], bH + q * 2);
#pragma unroll
                for (int mi = 0; mi < 2; mi++)
#pragma unroll
                    for (int q = 0; q < 2; q++)
                        mma_bf16(acc[mi][ni2 + q], aH[mi], bL + q * 2);
#pragma unroll
                for (int mi = 0; mi < 2; mi++)
#pragma unroll
                    for (int q = 0; q < 2; q++)
                        mma_bf16(acc[mi][ni2 + q], aL[mi], bH + q * 2);
            }
        }
    }

    // ---- GRU epilogue: gate g at ni = 2g+q; same (row, hid) per thread ------
    const int hidb = bx * 32 + wn * 16;
#pragma unroll
    for (int mi = 0; mi < 2; mi++) {
#pragma unroll
        for (int half = 0; half < 2; half++) {
            const int row = row0 + wm * 32 + mi * 16 + g + half * 8;
#pragma unroll
            for (int q = 0; q < 2; q++) {
                const int hid = hidb + q * 8 + tq * 2;
                float o2[2];
#pragma unroll
                for (int e = 0; e < 2; e++) {
                    const int j = half * 2 + e;
                    const float rv = sigf(acc[mi][0 + q][j] + cb4[hid + e]);
                    const float zv = sigf(acc[mi][2 + q][j] + cb4[256 + hid + e]);
                    const float nv = tanhf(acc[mi][4 + q][j] + cb4[512 + hid + e]
                                     + rv * (acc[mi][6 + q][j] + cb4[768 + hid + e]));
                    const float ho = h[(size_t)row * HID + hid + e];
                    o2[e] = (1.0f - zv) * nv + zv * ho;
                }
                *(float2*)(h + (size_t)row * HID + hid) = make_float2(o2[0], o2[1]);
                __nv_bfloat16 h0, l0, h1, l1;
                split1(o2[0], h0, l0);
                split1(o2[1], h1, l1);
                *(__nv_bfloat162*)(outH + (size_t)row * KD + hid) = __nv_bfloat162(h0, h1);
                *(__nv_bfloat162*)(outL + (size_t)row * KD + hid) = __nv_bfloat162(l0, l1);
            }
        }
    }
}

// ---------------- prep kernels -----------------------------------------------
__global__ void prep_x(const float* __restrict__ x,
                       __nv_bfloat16* __restrict__ xh, __nv_bfloat16* __restrict__ xl) {
    const int idx = blockIdx.x * 256 + threadIdx.x;
    if (idx >= NN * KD) return;
    const int row = idx >> 8, col = idx & 255;
    const float v = (row < NREAL && col < 200) ? x[row * 200 + col] : 0.0f;
    split1(v, xh[idx], xl[idx]);
}
__global__ void prep_wred(const float* __restrict__ W,
                          __nv_bfloat16* __restrict__ wh, __nv_bfloat16* __restrict__ wl) {
    const int idx = blockIdx.x * 256 + threadIdx.x;
    if (idx >= 256 * KD) return;
    const int n = idx >> 8, k = idx & 255;
    const float v = (k < 200) ? W[n * 200 + k] : 0.0f;
    split1(v, wh[idx], wl[idx]);
}
__global__ void prep_split(const float* __restrict__ W, int n,
                           __nv_bfloat16* __restrict__ wh, __nv_bfloat16* __restrict__ wl) {
    const int idx = blockIdx.x * 256 + threadIdx.x;
    if (idx >= n) return;
    split1(W[idx], wh[idx], wl[idx]);
}
// W_hh -> compact-hi: Whh rows gate'{0:r,1:z,2:n} -> slot = gate'.
__global__ void prep_whi(const float* __restrict__ Whh,
                         __nv_bfloat16* __restrict__ hiH, __nv_bfloat16* __restrict__ hiL) {
    const int idx = blockIdx.x * 256 + threadIdx.x;
    if (idx >= 768 * 256) return;
    const int o = idx >> 8, kk = idx & 255;
    const int gate = o >> 8, hid = o & 255;
    const int R = (hid >> 5) * 96 + ((hid >> 4) & 1) * 48 + gate * 16 + (hid & 15);
    __nv_bfloat16 hv, lv;
    split1(Whh[idx], hv, lv);
    hiH[(size_t)R * 256 + kk] = hv;
    hiL[(size_t)R * 256 + kk] = lv;
}
__global__ void prep_cb4(const float* __restrict__ bih, const float* __restrict__ bhh,
                         float* __restrict__ cb) {
    const int c = blockIdx.x * 256 + threadIdx.x;
    if (c >= 1024) return;
    const int gate = c >> 8, i = c & 255;
    float v;
    if (gate == 0)      v = bih[i] + bhh[i];
    else if (gate == 1) v = bih[256 + i] + bhh[256 + i];
    else if (gate == 2) v = bih[512 + i];
    else                v = bhh[512 + i];
    cb[c] = v;
}
__global__ void split_h(const float* __restrict__ h,
                        __nv_bfloat16* __restrict__ hh, __nv_bfloat16* __restrict__ hl) {
    const int idx = blockIdx.x * 256 + threadIdx.x;
    if (idx >= NN * HID) return;
    split1(h[idx], hh[idx], hl[idx]);
}

// ---------------- CSR build (parallel 3-phase scan) --------------------------
__global__ void hist_kernel(const int* __restrict__ ei, int* __restrict__ cnt) {
    const int e = blockIdx.x * 256 + threadIdx.x;
    if (e >= NE) return;
    atomicAdd(&cnt[ei[NE + e]], 1);
}
__global__ void scan_local(const int* __restrict__ cnt, int* __restrict__ rowptr,
                           int* __restrict__ bsum) {
    __shared__ int s[1024];
    const int tid = threadIdx.x;
    const int idx = blockIdx.x * 1024 + tid;
    int v = (idx < NN) ? cnt[idx] : 0;
    s[tid] = v;
    __syncthreads();
#pragma unroll
    for (int off = 1; off < 1024; off <<= 1) {
        int t = (tid >= off) ? s[tid - off] : 0;
        __syncthreads();
        s[tid] += t;
        __syncthreads();
    }
    if (idx < NN) rowptr[idx + 1] = s[tid];
    if (tid == 1023) bsum[blockIdx.x] = s[1023];
}
__global__ void scan_bsum(const int* __restrict__ bsum, int* __restrict__ boff) {
    if (threadIdx.x == 0) {
        int acc = 0;
        for (int i = 0; i < SCANB; i++) { boff[i] = acc; acc += bsum[i]; }
    }
}
__global__ void scan_add(int* __restrict__ rowptr, const int* __restrict__ boff) {
    const int idx = blockIdx.x * 1024 + threadIdx.x;
    if (idx == 0) rowptr[0] = 0;
    if (idx < NN) rowptr[idx + 1] += boff[blockIdx.x];
}
__global__ void copycur_kernel(const int* __restrict__ rowptr, int* __restrict__ cur) {
    const int i = blockIdx.x * 256 + threadIdx.x;
    if (i < NN) cur[i] = rowptr[i];
}
__global__ void fill_kernel(const int* __restrict__ ei, int* __restrict__ cur,
                            int* __restrict__ eidx) {
    const int e = blockIdx.x * 256 + threadIdx.x;
    if (e >= NE) return;
    const int pos = atomicAdd(&cur[ei[NE + e]], 1);
    eidx[pos] = ei[e];
}

// ---------------- aggregation: warp/dst-node gather of h -> bf16 planes ------
__global__ void agg_kernel(const float* __restrict__ h,
                           const int* __restrict__ rowptr, const int* __restrict__ eidx,
                           __nv_bfloat16* __restrict__ aggH, __nv_bfloat16* __restrict__ aggL)
{
    const int w = (blockIdx.x * blockDim.x + threadIdx.x) >> 5;
    const int lane = threadIdx.x & 31;
    if (w >= NN) return;
    const int beg = rowptr[w], end = rowptr[w + 1];
    float4 a0 = make_float4(0, 0, 0, 0), a1 = make_float4(0, 0, 0, 0);
    for (int i = beg; i < end; i++) {
        const int s = eidx[i];
        const float4* hr = (const float4*)(h + (size_t)s * 256);
        const float4 v0 = hr[lane * 2], v1 = hr[lane * 2 + 1];
        a0.x += v0.x; a0.y += v0.y; a0.z += v0.z; a0.w += v0.w;
        a1.x += v1.x; a1.y += v1.y; a1.z += v1.z; a1.w += v1.w;
    }
    const float vals[8] = {a0.x, a0.y, a0.z, a0.w, a1.x, a1.y, a1.z, a1.w};
    unsigned hb[4], lb[4];
#pragma unroll
    for (int q = 0; q < 4; q++) {
        __nv_bfloat16 h0, l0, h1, l1;
        split1(vals[2 * q], h0, l0);
        split1(vals[2 * q + 1], h1, l1);
        __nv_bfloat162 ph(h0, h1), pl(l0, l1);
        hb[q] = *(unsigned*)&ph;
        lb[q] = *(unsigned*)&pl;
    }
    *(uint4*)(aggH + (size_t)w * 256 + lane * 8) = make_uint4(hb[0], hb[1], hb[2], hb[3]);
    *(uint4*)(aggL + (size_t)w * 256 + lane * 8) = make_uint4(lb[0], lb[1], lb[2], lb[3]);
}

// ---------------- head -------------------------------------------------------
__global__ void head_kernel(const float* __restrict__ h,
                            const float* __restrict__ W_lin,
                            const float* __restrict__ b_lin,
                            float* __restrict__ out, int N)
{
    const int gt = blockIdx.x * blockDim.x + threadIdx.x;
    const int node = gt >> 5;
    const int lane = gt & 31;
    if (node >= N) return;
    const float4* hr = (const float4*)(h + (size_t)node * HID);
    const float4* w0 = (const float4*)(W_lin);
    const float4* w1 = (const float4*)(W_lin + HID);
    float a0 = 0.0f, a1 = 0.0f;
#pragma unroll
    for (int it = 0; it < 2; it++) {
        const int i = lane + it * 32;
        float4 v = hr[i];
        v.x = fmaxf(v.x, 0.f); v.y = fmaxf(v.y, 0.f);
        v.z = fmaxf(v.z, 0.f); v.w = fmaxf(v.w, 0.f);
        const float4 x0 = w0[i], x1 = w1[i];
        a0 += v.x * x0.x + v.y * x0.y + v.z * x0.z + v.w * x0.w;
        a1 += v.x * x1.x + v.y * x1.y + v.z * x1.z + v.w * x1.w;
    }
#pragma unroll
    for (int off = 16; off > 0; off >>= 1) {
        a0 += __shfl_down_sync(0xffffffffu, a0, off);
        a1 += __shfl_down_sync(0xffffffffu, a1, off);
    }
    if (lane == 0) {
        const float o0 = a0 + b_lin[0];
        const float o1 = a1 + b_lin[1];
        const float mx = fmaxf(o0, o1);
        const float lse = mx + logf(expf(o0 - mx) + expf(o1 - mx));
        out[(size_t)node * 2 + 0] = o0 - lse;
        out[(size_t)node * 2 + 1] = o1 - lse;
    }
}

// ---------------- launch -----------------------------------------------------
extern "C" void kernel_launch(void* const* d_in, const int* in_sizes, int n_in,
                              void* d_out, int out_size)
{
    const float* x        = (const float*)d_in[0];
    const int*   ei       = (const int*)  d_in[1];
    const float* W_reduce = (const float*)d_in[3];
    const float* b_reduce = (const float*)d_in[4];
    const float* W_ggc    = (const float*)d_in[5];
    const float* W_ih     = (const float*)d_in[6];
    const float* W_hh     = (const float*)d_in[7];
    const float* b_ih     = (const float*)d_in[8];
    const float* b_hh     = (const float*)d_in[9];
    const float* W_lin    = (const float*)d_in[10];
    const float* b_lin    = (const float*)d_in[11];
    float* out = (float*)d_out;

    float *h, *cb4;
    __nv_bfloat16 *hHa, *hLa, *hHb, *hLb, *xH, *xL, *aggH, *aggL;
    __nv_bfloat16 *WloH, *WloL, *WhiH, *WhiL, *WrH, *WrL, *WiH, *WiL, *WgH, *WgL;
    int *cnt, *rowptr, *cur, *eidx, *bsum, *boff;
    cudaGetSymbolAddress((void**)&h, g_h);
    cudaGetSymbolAddress((void**)&cb4, g_cb4);
    cudaGetSymbolAddress((void**)&hHa, g_hHa);
    cudaGetSymbolAddress((void**)&hLa, g_hLa);
    cudaGetSymbolAddress((void**)&hHb, g_hHb);
    cudaGetSymbolAddress((void**)&hLb, g_hLb);
    cudaGetSymbolAddress((void**)&xH, g_xH);
    cudaGetSymbolAddress((void**)&xL, g_xL);
    cudaGetSymbolAddress((void**)&aggH, g_aggH);
    cudaGetSymbolAddress((void**)&aggL, g_aggL);
    cudaGetSymbolAddress((void**)&WloH, g_WloH);
    cudaGetSymbolAddress((void**)&WloL, g_WloL);
    cudaGetSymbolAddress((void**)&WhiH, g_WhiH);
    cudaGetSymbolAddress((void**)&WhiL, g_WhiL);
    cudaGetSymbolAddress((void**)&WrH, g_WredH);
    cudaGetSymbolAddress((void**)&WrL, g_WredL);
    cudaGetSymbolAddress((void**)&WiH, g_WihH);
    cudaGetSymbolAddress((void**)&WiL, g_WihL);
    cudaGetSymbolAddress((void**)&WgH, g_WgH);
    cudaGetSymbolAddress((void**)&WgL, g_WgL);
    cudaGetSymbolAddress((void**)&cnt, g_cnt);
    cudaGetSymbolAddress((void**)&rowptr, g_rowptr);
    cudaGetSymbolAddress((void**)&cur, g_cur);
    cudaGetSymbolAddress((void**)&eidx, g_eidx);
    cudaGetSymbolAddress((void**)&bsum, g_bsum);
    cudaGetSymbolAddress((void**)&boff, g_boff);

    cudaFuncSetAttribute(gemm_init, cudaFuncAttributeMaxDynamicSharedMemorySize, GSMEM);
    cudaFuncSetAttribute(gemm_wfus, cudaFuncAttributeMaxDynamicSharedMemorySize, GSMEM);
    cudaFuncSetAttribute(gemm_gru,  cudaFuncAttributeMaxDynamicSharedMemorySize, GSMEMF);

    // ---- preprocessing ----
    prep_x<<<(NN * KD + 255) / 256, 256>>>(x, xH, xL);
    prep_wred<<<(256 * KD + 255) / 256, 256>>>(W_reduce, WrH, WrL);
    prep_split<<<(768 * KD + 255) / 256, 256>>>(W_ih, 768 * KD, WiH, WiL);
    prep_split<<<(NSTEP * 65536 + 255) / 256, 256>>>(W_ggc, NSTEP * 65536, WgH, WgL);
    gemm_wfus<<<dim3(2, 6, NSTEP), 256, GSMEM>>>(WiH, WiL, WgH, WgL, WloH, WloL);
    prep_whi<<<(768 * 256 + 255) / 256, 256>>>(W_hh, WhiH, WhiL);
    prep_cb4<<<4, 256>>>(b_ih, b_hh, cb4);
    cudaMemsetAsync(cnt, 0, NN * sizeof(int));
    hist_kernel<<<(NE + 255) / 256, 256>>>(ei, cnt);
    scan_local<<<SCANB, 1024>>>(cnt, rowptr, bsum);
    scan_bsum<<<1, 32>>>(bsum, boff);
    scan_add<<<SCANB, 1024>>>(rowptr, boff);
    copycur_kernel<<<(NN + 255) / 256, 256>>>(rowptr, cur);
    fill_kernel<<<(NE + 255) / 256, 256>>>(ei, cur, eidx);

    const int MB = NN / 128;   // 391

    // h = x @ W_reduce^T + b_reduce
    gemm_init<<<dim3(2, MB), 256, GSMEM>>>(xH, xL, WrH, WrL, b_reduce, h, 256);
    split_h<<<(NN * HID + 255) / 256, 256>>>(h, hHa, hLa);

    __nv_bfloat16 *inH = hHa, *inL = hLa, *otH = hHb, *otL = hLb;
    for (int t = 0; t < NSTEP; t++) {
        agg_kernel<<<(NN * 32 + 255) / 256, 256>>>(h, rowptr, eidx, aggH, aggL);
        gemm_gru<<<dim3(8, MB), 256, GSMEMF>>>(
            aggH, aggL, inH, inL,
            WloH + (size_t)t * 768 * 256, WloL + (size_t)t * 768 * 256,
            WhiH, WhiL, cb4, h, otH, otL);
        __nv_bfloat16* tmp;
        tmp = inH; inH = otH; otH = tmp;
        tmp = inL; inL = otL; otL = tmp;
    }

    head_kernel<<<(NREAL * 32 + 255) / 256, 256>>>(h, W_lin, b_lin, out, NREAL);
}

// round 14
// speedup vs baseline: 1.3766x; 1.3766x over previous
#include <cuda_runtime.h>
#include <cuda_bf16.h>
#include <math.h>
#include <stdint.h>

#define NN      50048      // padded node count (391 * 128)
#define NREAL   50000
#define NE      300000
#define KD      256
#define HID     256
#define NSTEP   8
#define SCANB   ((NN + 1023) / 1024)   // 49

// ---------------- scratch (static device globals; no runtime alloc) ----------
__device__ float g_h    [NN * HID];
__device__ float g_gates[NN * 1024];       // [r_sum | z_sum | i_n | h_n]
__device__ __nv_bfloat16 g_hH[NN * KD],   g_hL[NN * KD];
__device__ __nv_bfloat16 g_xH[NN * KD],   g_xL[NN * KD];
__device__ __nv_bfloat16 g_aggH[NN * KD], g_aggL[NN * KD];
__device__ __nv_bfloat16 g_WfusH[NSTEP * 768 * KD], g_WfusL[NSTEP * 768 * KD];
__device__ __nv_bfloat16 g_WhhH[768 * KD], g_WhhL[768 * KD];
__device__ __nv_bfloat16 g_WredH[256 * KD], g_WredL[256 * KD];
__device__ __nv_bfloat16 g_WihH[768 * KD], g_WihL[768 * KD];
__device__ __nv_bfloat16 g_WgH[NSTEP * 256 * 256], g_WgL[NSTEP * 256 * 256];
__device__ float g_cbias[1024];
__device__ int g_cnt[NN], g_rowptr[NN + 1], g_cur[NN], g_eidx[NE];
__device__ int g_bsum[SCANB], g_boff[SCANB];

// ---------------- shared GEMM machinery --------------------------------------
#define BK    32
#define SA    40                       // smem row stride in bf16 elems (80B)
#define PLANEB (128 * SA * 2)          // 10240 B
#define STAGEB (4 * PLANEB)            // 40960 B per stage
#define GSMEM  (2 * STAGEB)            // 81920 B

__device__ __forceinline__ void mma_bf16(float* c, const unsigned* a, const unsigned* b)
{
    asm volatile(
        "mma.sync.aligned.m16n8k16.row.col.f32.bf16.bf16.f32 "
        "{%0,%1,%2,%3}, {%4,%5,%6,%7}, {%8,%9}, {%0,%1,%2,%3};\n"
        : "+f"(c[0]), "+f"(c[1]), "+f"(c[2]), "+f"(c[3])
        : "r"(a[0]), "r"(a[1]), "r"(a[2]), "r"(a[3]), "r"(b[0]), "r"(b[1]));
}
__device__ __forceinline__ void ldsm4(unsigned* r, uint32_t addr)
{
    asm volatile("ldmatrix.sync.aligned.m8n8.x4.shared.b16 {%0,%1,%2,%3}, [%4];"
                 : "=r"(r[0]), "=r"(r[1]), "=r"(r[2]), "=r"(r[3]) : "r"(addr));
}
// streaming operand (no reuse): bypass L1
__device__ __forceinline__ void cpasync16(char* dst, const void* src)
{
    asm volatile("cp.async.cg.shared.global [%0], [%1], 16;"
                 :: "l"((uint64_t)__cvta_generic_to_shared(dst)), "l"(src) : "memory");
}
// weight operand (re-read by many CTAs per SM): allocate in L1
__device__ __forceinline__ void cpasync16_ca(char* dst, const void* src)
{
    asm volatile("cp.async.ca.shared.global [%0], [%1], 16;"
                 :: "l"((uint64_t)__cvta_generic_to_shared(dst)), "l"(src) : "memory");
}

#define GEMM_COMPUTE(base, BHOFF, BLOFF)                                       \
    do {                                                                       \
        _Pragma("unroll")                                                      \
        for (int ks = 0; ks < 2; ks++) {                                       \
            const uint32_t kso = ks * 32;                                      \
            unsigned aH[2][4], aL[2][4];                                       \
            ldsm4(aH[0], (base) + 0 * PLANEB + aoffH0 + kso);                  \
            ldsm4(aH[1], (base) + 0 * PLANEB + aoffH1 + kso);                  \
            ldsm4(aL[0], (base) + 1 * PLANEB + aoffH0 + kso);                  \
            ldsm4(aL[1], (base) + 1 * PLANEB + aoffH1 + kso);                  \
            _Pragma("unroll")                                                  \
            for (int ni2 = 0; ni2 < 8; ni2 += 2) {                             \
                unsigned bH[4], bL[4];                                         \
                const uint32_t bo = boff0 + (uint32_t)(ni2 * 8 * SA * 2) + kso;\
                ldsm4(bH, (base) + (BHOFF) + bo);                              \
                ldsm4(bL, (base) + (BLOFF) + bo);                              \
                _Pragma("unroll")                                              \
                for (int mi = 0; mi < 2; mi++)                                 \
                    _Pragma("unroll")                                          \
                    for (int q = 0; q < 2; q++)                                \
                        mma_bf16(acc[mi][ni2 + q], aH[mi], bH + q * 2);        \
                _Pragma("unroll")                                              \
                for (int mi = 0; mi < 2; mi++)                                 \
                    _Pragma("unroll")                                          \
                    for (int q = 0; q < 2; q++)                                \
                        mma_bf16(acc[mi][ni2 + q], aH[mi], bL + q * 2);        \
                _Pragma("unroll")                                              \
                for (int mi = 0; mi < 2; mi++)                                 \
                    _Pragma("unroll")                                          \
                    for (int q = 0; q < 2; q++)                                \
                        mma_bf16(acc[mi][ni2 + q], aL[mi], bH + q * 2);        \
            }                                                                  \
        }                                                                      \
    } while (0)

#define FRAG_SETUP()                                                           \
    const int tid  = threadIdx.x;                                              \
    const int lane = tid & 31;                                                 \
    const int warp = tid >> 5;                                                 \
    const int wm   = warp & 3;                                                 \
    const int wn   = warp >> 2;                                                \
    const int g    = lane >> 2;                                                \
    const int tq   = lane & 3;                                                 \
    const int a_row = wm * 32 + (lane & 15);                                   \
    const int a_kx  = (lane >> 4) * 16;                                        \
    const uint32_t aoffH0 = (uint32_t)(a_row * SA * 2 + a_kx);                 \
    const uint32_t aoffH1 = aoffH0 + 16 * SA * 2;                              \
    const int b_col = wn * 64 + (lane & 7) + ((lane >> 4) & 1) * 8;            \
    const int b_kx  = ((lane >> 3) & 1) * 16;                                  \
    const uint32_t boff0 = (uint32_t)(b_col * SA * 2 + b_kx)

#define ACC_INIT()                                                             \
    float acc[2][8][4];                                                        \
    _Pragma("unroll")                                                          \
    for (int mi = 0; mi < 2; mi++)                                             \
        _Pragma("unroll")                                                      \
        for (int ni = 0; ni < 8; ni++)                                         \
            _Pragma("unroll")                                                  \
            for (int j = 0; j < 4; j++) acc[mi][ni][j] = 0.0f

__device__ __forceinline__ void split1(float v, __nv_bfloat16& h, __nv_bfloat16& l) {
    h = __float2bfloat16(v);
    l = __float2bfloat16(v - __bfloat162float(h));
}
__device__ __forceinline__ float sigf(float x) { return 1.0f / (1.0f + __expf(-x)); }

// ---------------- init GEMM: C = A@B^T + bias --------------------------------
__global__ void __launch_bounds__(256, 2)
gemm_init(const __nv_bfloat16* __restrict__ AH, const __nv_bfloat16* __restrict__ AL,
          const __nv_bfloat16* __restrict__ BH, const __nv_bfloat16* __restrict__ BL,
          const float* __restrict__ bias, float* __restrict__ C, int ldc)
{
    extern __shared__ char sm[];
    const uint32_t sb = (uint32_t)__cvta_generic_to_shared(sm);
    FRAG_SETUP();
    const int row0 = blockIdx.y * 128, col0 = blockIdx.x * 128;
    const __nv_bfloat16* gp[4] = {AH, AL, BH, BL};

    auto copy_stage = [&](int st, int kc) {
        const int k0 = kc * BK;
        char* dst0 = sm + st * STAGEB;
#pragma unroll
        for (int i = 0; i < 8; i++) {
            const int idx = i * 256 + tid;
            const int p = idx >> 9, r = (idx >> 2) & 127, j = idx & 3;
            const int grow = ((p < 2) ? row0 : col0) + r;
            char* dst = dst0 + p * PLANEB + r * (SA * 2) + j * 16;
            const void* src = gp[p] + (size_t)grow * KD + k0 + j * 8;
            if (p < 2) cpasync16(dst, src);
            else       cpasync16_ca(dst, src);
        }
        asm volatile("cp.async.commit_group;" ::: "memory");
    };

    ACC_INIT();
    copy_stage(0, 0);
    const int NCHUNK = KD / BK;
    for (int c = 0; c < NCHUNK; c++) {
        asm volatile("cp.async.wait_group 0;" ::: "memory");
        __syncthreads();
        if (c + 1 < NCHUNK) copy_stage((c + 1) & 1, c + 1);
        GEMM_COMPUTE(sb + (c & 1) * STAGEB, 2 * PLANEB, 3 * PLANEB);
    }
#pragma unroll
    for (int mi = 0; mi < 2; mi++) {
        const int r = row0 + wm * 32 + mi * 16 + g;
#pragma unroll
        for (int ni = 0; ni < 8; ni++) {
            const int cc = col0 + wn * 64 + ni * 8 + tq * 2;
            const float b0 = bias[cc], b1 = bias[cc + 1];
            *(float2*)(C + (size_t)r * ldc + cc) =
                make_float2(acc[mi][ni][0] + b0, acc[mi][ni][1] + b1);
            *(float2*)(C + (size_t)(r + 8) * ldc + cc) =
                make_float2(acc[mi][ni][2] + b0, acc[mi][ni][3] + b1);
        }
    }
}

// ---------------- Wfused GEMM: Wfus[t] = Wih @ Wg_t^T ------------------------
__global__ void __launch_bounds__(256, 2)
gemm_wfus(const __nv_bfloat16* __restrict__ AH, const __nv_bfloat16* __restrict__ AL,
          const __nv_bfloat16* __restrict__ BHall, const __nv_bfloat16* __restrict__ BLall,
          __nv_bfloat16* __restrict__ fh, __nv_bfloat16* __restrict__ fl)
{
    extern __shared__ char sm[];
    const uint32_t sb = (uint32_t)__cvta_generic_to_shared(sm);
    FRAG_SETUP();
    const int row0 = blockIdx.y * 128, col0 = blockIdx.x * 128;
    const int t = blockIdx.z;
    const __nv_bfloat16* gp[4] = {AH, AL, BHall + (size_t)t * 65536,
                                  BLall + (size_t)t * 65536};

    auto copy_stage = [&](int st, int kc) {
        const int k0 = kc * BK;
        char* dst0 = sm + st * STAGEB;
#pragma unroll
        for (int i = 0; i < 8; i++) {
            const int idx = i * 256 + tid;
            const int p = idx >> 9, r = (idx >> 2) & 127, j = idx & 3;
            const int grow = ((p < 2) ? row0 : col0) + r;
            cpasync16_ca(dst0 + p * PLANEB + r * (SA * 2) + j * 16,
                         gp[p] + (size_t)grow * 256 + k0 + j * 8);
        }
        asm volatile("cp.async.commit_group;" ::: "memory");
    };

    ACC_INIT();
    copy_stage(0, 0);
    for (int c = 0; c < 8; c++) {
        asm volatile("cp.async.wait_group 0;" ::: "memory");
        __syncthreads();
        if (c + 1 < 8) copy_stage((c + 1) & 1, c + 1);
        GEMM_COMPUTE(sb + (c & 1) * STAGEB, 2 * PLANEB, 3 * PLANEB);
    }
    const size_t tb = (size_t)t * 768 * KD;
#pragma unroll
    for (int mi = 0; mi < 2; mi++) {
        const int r = row0 + wm * 32 + mi * 16 + g;
#pragma unroll
        for (int ni = 0; ni < 8; ni++) {
            const int cc = col0 + wn * 64 + ni * 8 + tq * 2;
#pragma unroll
            for (int j = 0; j < 4; j++) {
                const int o  = (j < 2) ? r : r + 8;
                const int kk = cc + (j & 1);
                __nv_bfloat16 hh, ll;
                split1(acc[mi][ni][j], hh, ll);
                fh[tb + (size_t)o * KD + kk] = hh;
                fl[tb + (size_t)o * KD + kk] = ll;
            }
        }
    }
}

// ---------------- step GEMM: gates = [agg|h] @ B'^T + cbias ------------------
__global__ void __launch_bounds__(256, 2)
gemm_step(const __nv_bfloat16* __restrict__ aggH, const __nv_bfloat16* __restrict__ aggL,
          const __nv_bfloat16* __restrict__ hH,   const __nv_bfloat16* __restrict__ hL,
          const __nv_bfloat16* __restrict__ WfH,  const __nv_bfloat16* __restrict__ WfL,
          const __nv_bfloat16* __restrict__ WhhH, const __nv_bfloat16* __restrict__ WhhL,
          const float* __restrict__ cbias, float* __restrict__ C)
{
    extern __shared__ char sm[];
    const uint32_t sb = (uint32_t)__cvta_generic_to_shared(sm);
    FRAG_SETUP();
    const int bx   = blockIdx.x;
    const int row0 = blockIdx.y * 128, col0 = bx * 128;

    int kbeg, kend;
    if (bx < 4)      { kbeg = 0; kend = 16; }
    else if (bx < 6) { kbeg = 0; kend = 8;  }
    else             { kbeg = 8; kend = 16; }

    auto copy_stage = [&](int st, int kc) {
        const int k0 = kc * BK;
        const bool hi = k0 >= 256;
        const int ka = hi ? k0 - 256 : k0;
        const __nv_bfloat16* aP[2] = { hi ? hH : aggH, hi ? hL : aggL };
        char* dst0 = sm + st * STAGEB;
#pragma unroll
        for (int i = 0; i < 8; i++) {
            const int idx = i * 256 + tid;
            const int p = idx >> 9, r = (idx >> 2) & 127, j = idx & 3;
            char* dst = dst0 + p * PLANEB + r * (SA * 2) + j * 16;
            if (p < 2) {
                cpasync16(dst, aP[p] + (size_t)(row0 + r) * KD + ka + j * 8);
            } else {
                const int c = col0 + r;
                const __nv_bfloat16* W;
                if (hi) W = ((p == 3) ? WhhL : WhhH)
                            + (size_t)((c < 768) ? c : c - 256) * KD + ka;
                else    W = ((p == 3) ? WfL : WfH) + (size_t)c * KD + ka;
                cpasync16_ca(dst, W + j * 8);
            }
        }
        asm volatile("cp.async.commit_group;" ::: "memory");
    };

    ACC_INIT();
    copy_stage(0, kbeg);
    for (int c = kbeg; c < kend; c++) {
        asm volatile("cp.async.wait_group 0;" ::: "memory");
        __syncthreads();
        if (c + 1 < kend) copy_stage((c + 1 - kbeg) & 1, c + 1);
        GEMM_COMPUTE(sb + ((c - kbeg) & 1) * STAGEB, 2 * PLANEB, 3 * PLANEB);
    }
#pragma unroll
    for (int mi = 0; mi < 2; mi++) {
        const int r = row0 + wm * 32 + mi * 16 + g;
#pragma unroll
        for (int ni = 0; ni < 8; ni++) {
            const int cc = col0 + wn * 64 + ni * 8 + tq * 2;
            const float b0 = cbias[cc], b1 = cbias[cc + 1];
            *(float2*)(C + (size_t)r * 1024 + cc) =
                make_float2(acc[mi][ni][0] + b0, acc[mi][ni][1] + b1);
            *(float2*)(C + (size_t)(r + 8) * 1024 + cc) =
                make_float2(acc[mi][ni][2] + b0, acc[mi][ni][3] + b1);
        }
    }
}

// ---------------- prep kernels -----------------------------------------------
__global__ void prep_x(const float* __restrict__ x,
                       __nv_bfloat16* __restrict__ xh, __nv_bfloat16* __restrict__ xl) {
    const int idx = blockIdx.x * 256 + threadIdx.x;
    if (idx >= NN * KD) return;
    const int row = idx >> 8, col = idx & 255;
    const float v = (row < NREAL && col < 200) ? x[row * 200 + col] : 0.0f;
    split1(v, xh[idx], xl[idx]);
}
__global__ void prep_wred(const float* __restrict__ W,
                          __nv_bfloat16* __restrict__ wh, __nv_bfloat16* __restrict__ wl) {
    const int idx = blockIdx.x * 256 + threadIdx.x;
    if (idx >= 256 * KD) return;
    const int n = idx >> 8, k = idx & 255;
    const float v = (k < 200) ? W[n * 200 + k] : 0.0f;
    split1(v, wh[idx], wl[idx]);
}
__global__ void prep_split(const float* __restrict__ W, int n,
                           __nv_bfloat16* __restrict__ wh, __nv_bfloat16* __restrict__ wl) {
    const int idx = blockIdx.x * 256 + threadIdx.x;
    if (idx >= n) return;
    split1(W[idx], wh[idx], wl[idx]);
}
__global__ void prep_cbias(const float* __restrict__ bih, const float* __restrict__ bhh,
                           float* __restrict__ cb) {
    const int c = blockIdx.x * 256 + threadIdx.x;
    if (c >= 1024) return;
    float v;
    if (c < 512)       v = bih[c] + bhh[c];
    else if (c < 768)  v = bih[c];
    else               v = bhh[c - 256];
    cb[c] = v;
}
__global__ void split_h(const float* __restrict__ h,
                        __nv_bfloat16* __restrict__ hh, __nv_bfloat16* __restrict__ hl) {
    const int idx = blockIdx.x * 256 + threadIdx.x;
    if (idx >= NN * HID) return;
    split1(h[idx], hh[idx], hl[idx]);
}

// ---------------- CSR build (parallel 3-phase scan) --------------------------
__global__ void hist_kernel(const int* __restrict__ ei, int* __restrict__ cnt) {
    const int e = blockIdx.x * 256 + threadIdx.x;
    if (e >= NE) return;
    atomicAdd(&cnt[ei[NE + e]], 1);
}
__global__ void scan_local(const int* __restrict__ cnt, int* __restrict__ rowptr,
                           int* __restrict__ bsum) {
    __shared__ int s[1024];
    const int tid = threadIdx.x;
    const int idx = blockIdx.x * 1024 + tid;
    int v = (idx < NN) ? cnt[idx] : 0;
    s[tid] = v;
    __syncthreads();
#pragma unroll
    for (int off = 1; off < 1024; off <<= 1) {
        int t = (tid >= off) ? s[tid - off] : 0;
        __syncthreads();
        s[tid] += t;
        __syncthreads();
    }
    if (idx < NN) rowptr[idx + 1] = s[tid];
    if (tid == 1023) bsum[blockIdx.x] = s[1023];
}
__global__ void scan_bsum(const int* __restrict__ bsum, int* __restrict__ boff) {
    if (threadIdx.x == 0) {
        int acc = 0;
        for (int i = 0; i < SCANB; i++) { boff[i] = acc; acc += bsum[i]; }
    }
}
__global__ void scan_add(int* __restrict__ rowptr, const int* __restrict__ boff) {
    const int idx = blockIdx.x * 1024 + threadIdx.x;
    if (idx == 0) rowptr[0] = 0;
    if (idx < NN) rowptr[idx + 1] += boff[blockIdx.x];
}
__global__ void copycur_kernel(const int* __restrict__ rowptr, int* __restrict__ cur) {
    const int i = blockIdx.x * 256 + threadIdx.x;
    if (i < NN) cur[i] = rowptr[i];
}
__global__ void fill_kernel(const int* __restrict__ ei, int* __restrict__ cur,
                            int* __restrict__ eidx) {
    const int e = blockIdx.x * 256 + threadIdx.x;
    if (e >= NE) return;
    const int pos = atomicAdd(&cur[ei[NE + e]], 1);
    eidx[pos] = ei[e];
}

// ---------------- aggregation: warp/dst-node gather of h -> bf16 planes ------
__global__ void agg_kernel(const float* __restrict__ h,
                           const int* __restrict__ rowptr, const int* __restrict__ eidx,
                           __nv_bfloat16* __restrict__ aggH, __nv_bfloat16* __restrict__ aggL)
{
    const int w = (blockIdx.x * blockDim.x + threadIdx.x) >> 5;
    const int lane = threadIdx.x & 31;
    if (w >= NN) return;
    const int beg = rowptr[w], end = rowptr[w + 1];
    float4 a0 = make_float4(0, 0, 0, 0), a1 = make_float4(0, 0, 0, 0);
    for (int i = beg; i < end; i++) {
        const int s = eidx[i];
        const float4* hr = (const float4*)(h + (size_t)s * 256);
        const float4 v0 = hr[lane * 2], v1 = hr[lane * 2 + 1];
        a0.x += v0.x; a0.y += v0.y; a0.z += v0.z; a0.w += v0.w;
        a1.x += v1.x; a1.y += v1.y; a1.z += v1.z; a1.w += v1.w;
    }
    const float vals[8] = {a0.x, a0.y, a0.z, a0.w, a1.x, a1.y, a1.z, a1.w};
    unsigned hb[4], lb[4];
#pragma unroll
    for (int q = 0; q < 4; q++) {
        __nv_bfloat16 h0, l0, h1, l1;
        split1(vals[2 * q], h0, l0);
        split1(vals[2 * q + 1], h1, l1);
        __nv_bfloat162 ph(h0, h1), pl(l0, l1);
        hb[q] = *(unsigned*)&ph;
        lb[q] = *(unsigned*)&pl;
    }
    *(uint4*)(aggH + (size_t)w * 256 + lane * 8) = make_uint4(hb[0], hb[1], hb[2], hb[3]);
    *(uint4*)(aggL + (size_t)w * 256 + lane * 8) = make_uint4(lb[0], lb[1], lb[2], lb[3]);
}

// ---------------- fused GRU (reads pre-summed gates) -------------------------
__global__ void gru_kernel(const float* __restrict__ gates,
                           float* __restrict__ h,
                           __nv_bfloat16* __restrict__ hh, __nv_bfloat16* __restrict__ hl)
{
    const int idx = blockIdx.x * blockDim.x + threadIdx.x;
    if (idx >= NN * 64) return;
    const int row = idx >> 6, c = (idx & 63) * 4;
    const float* G = gates + (size_t)row * 1024;
    const float4 rs = *(const float4*)(G + c);
    const float4 zs = *(const float4*)(G + 256 + c);
    const float4 iv = *(const float4*)(G + 512 + c);
    const float4 hv2 = *(const float4*)(G + 768 + c);
    float4* H = (float4*)(h + (size_t)row * 256 + c);
    const float4 hv = *H;

    float4 o;
    { float r = sigf(rs.x), z = sigf(zs.x);
      float n = tanhf(iv.x + r * hv2.x); o.x = (1.0f - z) * n + z * hv.x; }
    { float r = sigf(rs.y), z = sigf(zs.y);
      float n = tanhf(iv.y + r * hv2.y); o.y = (1.0f - z) * n + z * hv.y; }
    { float r = sigf(rs.z), z = sigf(zs.z);
      float n = tanhf(iv.z + r * hv2.z); o.z = (1.0f - z) * n + z * hv.z; }
    { float r = sigf(rs.w), z = sigf(zs.w);
      float n = tanhf(iv.w + r * hv2.w); o.w = (1.0f - z) * n + z * hv.w; }
    *H = o;

    __nv_bfloat16 h0, l0, h1, l1, h2, l2, h3, l3;
    split1(o.x, h0, l0); split1(o.y, h1, l1);
    split1(o.z, h2, l2); split1(o.w, h3, l3);
    __nv_bfloat162 p01(h0, h1), p23(h2, h3), q01(l0, l1), q23(l2, l3);
    *(__nv_bfloat162*)(hh + (size_t)row * 256 + c)     = p01;
    *(__nv_bfloat162*)(hh + (size_t)row * 256 + c + 2) = p23;
    *(__nv_bfloat162*)(hl + (size_t)row * 256 + c)     = q01;
    *(__nv_bfloat162*)(hl + (size_t)row * 256 + c + 2) = q23;
}

// ---------------- head -------------------------------------------------------
__global__ void head_kernel(const float* __restrict__ h,
                            const float* __restrict__ W_lin,
                            const float* __restrict__ b_lin,
                            float* __restrict__ out, int N)
{
    const int gt = blockIdx.x * blockDim.x + threadIdx.x;
    const int node = gt >> 5;
    const int lane = gt & 31;
    if (node >= N) return;
    const float4* hr = (const float4*)(h + (size_t)node * HID);
    const float4* w0 = (const float4*)(W_lin);
    const float4* w1 = (const float4*)(W_lin + HID);
    float a0 = 0.0f, a1 = 0.0f;
#pragma unroll
    for (int it = 0; it < 2; it++) {
        const int i = lane + it * 32;
        float4 v = hr[i];
        v.x = fmaxf(v.x, 0.f); v.y = fmaxf(v.y, 0.f);
        v.z = fmaxf(v.z, 0.f); v.w = fmaxf(v.w, 0.f);
        const float4 x0 = w0[i], x1 = w1[i];
        a0 += v.x * x0.x + v.y * x0.y + v.z * x0.z + v.w * x0.w;
        a1 += v.x * x1.x + v.y * x1.y + v.z * x1.z + v.w * x1.w;
    }
#pragma unroll
    for (int off = 16; off > 0; off >>= 1) {
        a0 += __shfl_down_sync(0xffffffffu, a0, off);
        a1 += __shfl_down_sync(0xffffffffu, a1, off);
    }
    if (lane == 0) {
        const float o0 = a0 + b_lin[0];
        const float o1 = a1 + b_lin[1];
        const float mx = fmaxf(o0, o1);
        const float lse = mx + logf(expf(o0 - mx) + expf(o1 - mx));
        out[(size_t)node * 2 + 0] = o0 - lse;
        out[(size_t)node * 2 + 1] = o1 - lse;
    }
}

// ---------------- launch -----------------------------------------------------
extern "C" void kernel_launch(void* const* d_in, const int* in_sizes, int n_in,
                              void* d_out, int out_size)
{
    const float* x        = (const float*)d_in[0];
    const int*   ei       = (const int*)  d_in[1];
    const float* W_reduce = (const float*)d_in[3];
    const float* b_reduce = (const float*)d_in[4];
    const float* W_ggc    = (const float*)d_in[5];
    const float* W_ih     = (const float*)d_in[6];
    const float* W_hh     = (const float*)d_in[7];
    const float* b_ih     = (const float*)d_in[8];
    const float* b_hh     = (const float*)d_in[9];
    const float* W_lin    = (const float*)d_in[10];
    const float* b_lin    = (const float*)d_in[11];
    float* out = (float*)d_out;

    float *h, *gates, *cbias;
    __nv_bfloat16 *hH, *hL, *xH, *xL, *aggH, *aggL, *WfH, *WfL, *WhH, *WhL, *WrH, *WrL;
    __nv_bfloat16 *WiH, *WiL, *WgH, *WgL;
    int *cnt, *rowptr, *cur, *eidx, *bsum, *boff;
    cudaGetSymbolAddress((void**)&h, g_h);
    cudaGetSymbolAddress((void**)&gates, g_gates);
    cudaGetSymbolAddress((void**)&cbias, g_cbias);
    cudaGetSymbolAddress((void**)&hH, g_hH);
    cudaGetSymbolAddress((void**)&hL, g_hL);
    cudaGetSymbolAddress((void**)&xH, g_xH);
    cudaGetSymbolAddress((void**)&xL, g_xL);
    cudaGetSymbolAddress((void**)&aggH, g_aggH);
    cudaGetSymbolAddress((void**)&aggL, g_aggL);
    cudaGetSymbolAddress((void**)&WfH, g_WfusH);
    cudaGetSymbolAddress((void**)&WfL, g_WfusL);
    cudaGetSymbolAddress((void**)&WhH, g_WhhH);
    cudaGetSymbolAddress((void**)&WhL, g_WhhL);
    cudaGetSymbolAddress((void**)&WrH, g_WredH);
    cudaGetSymbolAddress((void**)&WrL, g_WredL);
    cudaGetSymbolAddress((void**)&WiH, g_WihH);
    cudaGetSymbolAddress((void**)&WiL, g_WihL);
    cudaGetSymbolAddress((void**)&WgH, g_WgH);
    cudaGetSymbolAddress((void**)&WgL, g_WgL);
    cudaGetSymbolAddress((void**)&cnt, g_cnt);
    cudaGetSymbolAddress((void**)&rowptr, g_rowptr);
    cudaGetSymbolAddress((void**)&cur, g_cur);
    cudaGetSymbolAddress((void**)&eidx, g_eidx);
    cudaGetSymbolAddress((void**)&bsum, g_bsum);
    cudaGetSymbolAddress((void**)&boff, g_boff);

    cudaFuncSetAttribute(gemm_init, cudaFuncAttributeMaxDynamicSharedMemorySize, GSMEM);
    cudaFuncSetAttribute(gemm_step, cudaFuncAttributeMaxDynamicSharedMemorySize, GSMEM);
    cudaFuncSetAttribute(gemm_wfus, cudaFuncAttributeMaxDynamicSharedMemorySize, GSMEM);

    // ---- preprocessing ----
    prep_x<<<(NN * KD + 255) / 256, 256>>>(x, xH, xL);
    prep_wred<<<(256 * KD + 255) / 256, 256>>>(W_reduce, WrH, WrL);
    prep_split<<<(768 * KD + 255) / 256, 256>>>(W_hh, 768 * KD, WhH, WhL);
    prep_split<<<(768 * KD + 255) / 256, 256>>>(W_ih, 768 * KD, WiH, WiL);
    prep_split<<<(NSTEP * 65536 + 255) / 256, 256>>>(W_ggc, NSTEP * 65536, WgH, WgL);
    gemm_wfus<<<dim3(2, 6, NSTEP), 256, GSMEM>>>(WiH, WiL, WgH, WgL, WfH, WfL);
    prep_cbias<<<4, 256>>>(b_ih, b_hh, cbias);
    cudaMemsetAsync(cnt, 0, NN * sizeof(int));
    hist_kernel<<<(NE + 255) / 256, 256>>>(ei, cnt);
    scan_local<<<SCANB, 1024>>>(cnt, rowptr, bsum);
    scan_bsum<<<1, 32>>>(bsum, boff);
    scan_add<<<SCANB, 1024>>>(rowptr, boff);
    copycur_kernel<<<(NN + 255) / 256, 256>>>(rowptr, cur);
    fill_kernel<<<(NE + 255) / 256, 256>>>(ei, cur, eidx);

    const int MB = NN / 128;   // 391

    // h = x @ W_reduce^T + b_reduce
    gemm_init<<<dim3(2, MB), 256, GSMEM>>>(xH, xL, WrH, WrL, b_reduce, h, 256);
    split_h<<<(NN * HID + 255) / 256, 256>>>(h, hH, hL);

    for (int t = 0; t < NSTEP; t++) {
        agg_kernel<<<(NN * 32 + 255) / 256, 256>>>(h, rowptr, eidx, aggH, aggL);
        gemm_step<<<dim3(8, MB), 256, GSMEM>>>(
            aggH, aggL, hH, hL,
            WfH + (size_t)t * 768 * KD, WfL + (size_t)t * 768 * KD,
            WhH, WhL, cbias, gates);
        gru_kernel<<<(NN * 64 + 255) / 256, 256>>>(gates, h, hH, hL);
    }

    head_kernel<<<(NREAL * 32 + 255) / 256, 256>>>(h, W_lin, b_lin, out, NREAL);
}

// round 15
// speedup vs baseline: 1.7354x; 1.2607x over previous
#include <cuda_runtime.h>
#include <cuda_fp16.h>
#include <math.h>
#include <stdint.h>

#define NN      50048      // padded node count (391 * 128)
#define NREAL   50000
#define NE      300000
#define KD      256
#define HID     256
#define NSTEP   8
#define SCANB   ((NN + 1023) / 1024)   // 49

// ---------------- scratch (static device globals; no runtime alloc) ----------
__device__ float g_h    [NN * HID];
__device__ float g_gates[NN * 1024];       // [r_sum | z_sum | i_n | h_n]
__device__ __half g_hF[NN * KD];
__device__ __half g_xF[NN * KD];
__device__ __half g_aggF[NN * KD];
__device__ __half g_WfusH[NSTEP * 768 * KD], g_WfusL[NSTEP * 768 * KD];
__device__ __half g_WhhH[768 * KD], g_WhhL[768 * KD];
__device__ __half g_WredH[256 * KD], g_WredL[256 * KD];
__device__ __half g_WihH[768 * KD], g_WihL[768 * KD];
__device__ __half g_WgH[NSTEP * 256 * 256], g_WgL[NSTEP * 256 * 256];
__device__ float g_cbias[1024];
__device__ int g_cnt[NN], g_rowptr[NN + 1], g_cur[NN], g_eidx[NE];
__device__ int g_bsum[SCANB], g_boff[SCANB];

// ---------------- shared GEMM machinery --------------------------------------
#define BK    32
#define SA    40                       // smem row stride in fp16 elems (80B)
#define PLANEB (128 * SA * 2)          // 10240 B
#define STG3P  (3 * PLANEB)            // 30720 B (2-product stage: A, Bh, Bl)
#define GSMEM3 (3 * STG3P)             // 92160 B (3 stages)
#define STG4P  (4 * PLANEB)            // 40960 B (3-product stage)
#define GSMEM4 (2 * STG4P)             // 81920 B

__device__ __forceinline__ void mma_f16(float* c, const unsigned* a, const unsigned* b)
{
    asm volatile(
        "mma.sync.aligned.m16n8k16.row.col.f32.f16.f16.f32 "
        "{%0,%1,%2,%3}, {%4,%5,%6,%7}, {%8,%9}, {%0,%1,%2,%3};\n"
        : "+f"(c[0]), "+f"(c[1]), "+f"(c[2]), "+f"(c[3])
        : "r"(a[0]), "r"(a[1]), "r"(a[2]), "r"(a[3]), "r"(b[0]), "r"(b[1]));
}
__device__ __forceinline__ void ldsm4(unsigned* r, uint32_t addr)
{
    asm volatile("ldmatrix.sync.aligned.m8n8.x4.shared.b16 {%0,%1,%2,%3}, [%4];"
                 : "=r"(r[0]), "=r"(r[1]), "=r"(r[2]), "=r"(r[3]) : "r"(addr));
}
__device__ __forceinline__ void cpasync16(char* dst, const void* src)
{
    asm volatile("cp.async.cg.shared.global [%0], [%1], 16;"
                 :: "l"((uint64_t)__cvta_generic_to_shared(dst)), "l"(src) : "memory");
}

// 2-product compute: C += A*(Bh) + A*(Bl).  Planes: A@0, Bh@PLANEB, Bl@2*PLANEB.
#define GEMM2P(base)                                                           \
    do {                                                                       \
        _Pragma("unroll")                                                      \
        for (int ks = 0; ks < 2; ks++) {                                       \
            const uint32_t kso = ks * 32;                                      \
            unsigned aF[2][4];                                                 \
            ldsm4(aF[0], (base) + aoffH0 + kso);                               \
            ldsm4(aF[1], (base) + aoffH1 + kso);                               \
            _Pragma("unroll")                                                  \
            for (int ni2 = 0; ni2 < 8; ni2 += 2) {                             \
                unsigned bH[4], bL[4];                                         \
                const uint32_t bo = boff0 + (uint32_t)(ni2 * 8 * SA * 2) + kso;\
                ldsm4(bH, (base) + 1 * PLANEB + bo);                           \
                ldsm4(bL, (base) + 2 * PLANEB + bo);                           \
                _Pragma("unroll")                                              \
                for (int mi = 0; mi < 2; mi++)                                 \
                    _Pragma("unroll")                                          \
                    for (int q = 0; q < 2; q++)                                \
                        mma_f16(acc[mi][ni2 + q], aF[mi], bH + q * 2);         \
                _Pragma("unroll")                                              \
                for (int mi = 0; mi < 2; mi++)                                 \
                    _Pragma("unroll")                                          \
                    for (int q = 0; q < 2; q++)                                \
                        mma_f16(acc[mi][ni2 + q], aF[mi], bL + q * 2);         \
            }                                                                  \
        }                                                                      \
    } while (0)

// 3-product compute (wfus only): planes Ah@0, Al@1, Bh@2, Bl@3.
#define GEMM3P(base)                                                           \
    do {                                                                       \
        _Pragma("unroll")                                                      \
        for (int ks = 0; ks < 2; ks++) {                                       \
            const uint32_t kso = ks * 32;                                      \
            unsigned aH[2][4], aL[2][4];                                       \
            ldsm4(aH[0], (base) + 0 * PLANEB + aoffH0 + kso);                  \
            ldsm4(aH[1], (base) + 0 * PLANEB + aoffH1 + kso);                  \
            ldsm4(aL[0], (base) + 1 * PLANEB + aoffH0 + kso);                  \
            ldsm4(aL[1], (base) + 1 * PLANEB + aoffH1 + kso);                  \
            _Pragma("unroll")                                                  \
            for (int ni2 = 0; ni2 < 8; ni2 += 2) {                             \
                unsigned bH[4], bL[4];                                         \
                const uint32_t bo = boff0 + (uint32_t)(ni2 * 8 * SA * 2) + kso;\
                ldsm4(bH, (base) + 2 * PLANEB + bo);                           \
                ldsm4(bL, (base) + 3 * PLANEB + bo);                           \
                _Pragma("unroll")                                              \
                for (int mi = 0; mi < 2; mi++)                                 \
                    _Pragma("unroll")                                          \
                    for (int q = 0; q < 2; q++)                                \
                        mma_f16(acc[mi][ni2 + q], aH[mi], bH + q * 2);         \
                _Pragma("unroll")                                              \
                for (int mi = 0; mi < 2; mi++)                                 \
                    _Pragma("unroll")                                          \
                    for (int q = 0; q < 2; q++)                                \
                        mma_f16(acc[mi][ni2 + q], aH[mi], bL + q * 2);         \
                _Pragma("unroll")                                              \
                for (int mi = 0; mi < 2; mi++)                                 \
                    _Pragma("unroll")                                          \
                    for (int q = 0; q < 2; q++)                                \
                        mma_f16(acc[mi][ni2 + q], aL[mi], bH + q * 2);         \
            }                                                                  \
        }                                                                      \
    } while (0)

#define FRAG_SETUP()                                                           \
    const int tid  = threadIdx.x;                                              \
    const int lane = tid & 31;                                                 \
    const int warp = tid >> 5;                                                 \
    const int wm   = warp & 3;                                                 \
    const int wn   = warp >> 2;                                                \
    const int g    = lane >> 2;                                                \
    const int tq   = lane & 3;                                                 \
    const int a_row = wm * 32 + (lane & 15);                                   \
    const int a_kx  = (lane >> 4) * 16;                                        \
    const uint32_t aoffH0 = (uint32_t)(a_row * SA * 2 + a_kx);                 \
    const uint32_t aoffH1 = aoffH0 + 16 * SA * 2;                              \
    const int b_col = wn * 64 + (lane & 7) + ((lane >> 4) & 1) * 8;            \
    const int b_kx  = ((lane >> 3) & 1) * 16;                                  \
    const uint32_t boff0 = (uint32_t)(b_col * SA * 2 + b_kx)

#define ACC_INIT()                                                             \
    float acc[2][8][4];                                                        \
    _Pragma("unroll")                                                          \
    for (int mi = 0; mi < 2; mi++)                                             \
        _Pragma("unroll")                                                      \
        for (int ni = 0; ni < 8; ni++)                                         \
            _Pragma("unroll")                                                  \
            for (int j = 0; j < 4; j++) acc[mi][ni][j] = 0.0f

__device__ __forceinline__ void split1h(float v, __half& h, __half& l) {
    h = __float2half(v);
    l = __float2half(v - __half2float(h));
}
__device__ __forceinline__ float sigf(float x) { return 1.0f / (1.0f + __expf(-x)); }

// ---------------- init GEMM: h = xF @ [WredH+WredL]^T + bias -----------------
__global__ void __launch_bounds__(256, 2)
gemm_init(const __half* __restrict__ AF,
          const __half* __restrict__ BH, const __half* __restrict__ BL,
          const float* __restrict__ bias, float* __restrict__ C, int ldc)
{
    extern __shared__ char sm[];
    const uint32_t sb = (uint32_t)__cvta_generic_to_shared(sm);
    FRAG_SETUP();
    const int row0 = blockIdx.y * 128, col0 = blockIdx.x * 128;

    auto copy_stage = [&](int st, int kc) {
        const int k0 = kc * BK;
        char* d = sm + st * STG3P;
#pragma unroll
        for (int i = 0; i < 6; i++) {
            const int idx = i * 256 + tid;             // 0..1535
            if (idx < 512) {
                const int r = idx >> 2, j = idx & 3;
                cpasync16(d + r * (SA * 2) + j * 16,
                          AF + (size_t)(row0 + r) * KD + k0 + j * 8);
            } else {
                const int rb = idx - 512;
                const int p = rb >> 9, rr = rb & 511;
                const int r = rr >> 2, j = rr & 3;
                cpasync16(d + (1 + p) * PLANEB + r * (SA * 2) + j * 16,
                          (p ? BL : BH) + (size_t)(col0 + r) * KD + k0 + j * 8);
            }
        }
        asm volatile("cp.async.commit_group;" ::: "memory");
    };

    ACC_INIT();
    const int NC = KD / BK;
    copy_stage(0, 0);
    copy_stage(1, 1);
    for (int c = 0; c < NC; c++) {
        if (c + 1 < NC) asm volatile("cp.async.wait_group 1;" ::: "memory");
        else            asm volatile("cp.async.wait_group 0;" ::: "memory");
        __syncthreads();
        if (c + 2 < NC) copy_stage((c + 2) % 3, c + 2);
        GEMM2P(sb + (uint32_t)((c % 3) * STG3P));
    }
#pragma unroll
    for (int mi = 0; mi < 2; mi++) {
        const int r = row0 + wm * 32 + mi * 16 + g;
#pragma unroll
        for (int ni = 0; ni < 8; ni++) {
            const int cc = col0 + wn * 64 + ni * 8 + tq * 2;
            const float b0 = bias[cc], b1 = bias[cc + 1];
            *(float2*)(C + (size_t)r * ldc + cc) =
                make_float2(acc[mi][ni][0] + b0, acc[mi][ni][1] + b1);
            *(float2*)(C + (size_t)(r + 8) * ldc + cc) =
                make_float2(acc[mi][ni][2] + b0, acc[mi][ni][3] + b1);
        }
    }
}

// ---------------- Wfused GEMM (3-product fp16): Wfus[t] = Wih @ Wg_t^T -------
__global__ void __launch_bounds__(256, 2)
gemm_wfus(const __half* __restrict__ AH, const __half* __restrict__ AL,
          const __half* __restrict__ BHall, const __half* __restrict__ BLall,
          __half* __restrict__ fh, __half* __restrict__ fl)
{
    extern __shared__ char sm[];
    const uint32_t sb = (uint32_t)__cvta_generic_to_shared(sm);
    FRAG_SETUP();
    const int row0 = blockIdx.y * 128, col0 = blockIdx.x * 128;
    const int t = blockIdx.z;
    const __half* gp[4] = {AH, AL, BHall + (size_t)t * 65536,
                           BLall + (size_t)t * 65536};

    auto copy_stage = [&](int st, int kc) {
        const int k0 = kc * BK;
        char* dst0 = sm + st * STG4P;
#pragma unroll
        for (int i = 0; i < 8; i++) {
            const int idx = i * 256 + tid;
            const int p = idx >> 9, r = (idx >> 2) & 127, j = idx & 3;
            const int grow = ((p < 2) ? row0 : col0) + r;
            cpasync16(dst0 + p * PLANEB + r * (SA * 2) + j * 16,
                      gp[p] + (size_t)grow * 256 + k0 + j * 8);
        }
        asm volatile("cp.async.commit_group;" ::: "memory");
    };

    ACC_INIT();
    copy_stage(0, 0);
    for (int c = 0; c < 8; c++) {
        asm volatile("cp.async.wait_group 0;" ::: "memory");
        __syncthreads();
        if (c + 1 < 8) copy_stage((c + 1) & 1, c + 1);
        GEMM3P(sb + (c & 1) * STG4P);
    }
    const size_t tb = (size_t)t * 768 * KD;
#pragma unroll
    for (int mi = 0; mi < 2; mi++) {
        const int r = row0 + wm * 32 + mi * 16 + g;
#pragma unroll
        for (int ni = 0; ni < 8; ni++) {
            const int cc = col0 + wn * 64 + ni * 8 + tq * 2;
#pragma unroll
            for (int j = 0; j < 4; j++) {
                const int o  = (j < 2) ? r : r + 8;
                const int kk = cc + (j & 1);
                __half hh, ll;
                split1h(acc[mi][ni][j], hh, ll);
                fh[tb + (size_t)o * KD + kk] = hh;
                fl[tb + (size_t)o * KD + kk] = ll;
            }
        }
    }
}

// ---------------- step GEMM: gates = [aggF|hF] @ B'^T + cbias ----------------
__global__ void __launch_bounds__(256, 2)
gemm_step(const __half* __restrict__ aggF, const __half* __restrict__ hF,
          const __half* __restrict__ WfH,  const __half* __restrict__ WfL,
          const __half* __restrict__ WhhH, const __half* __restrict__ WhhL,
          const float* __restrict__ cbias, float* __restrict__ C)
{
    extern __shared__ char sm[];
    const uint32_t sb = (uint32_t)__cvta_generic_to_shared(sm);
    FRAG_SETUP();
    const int bx   = blockIdx.x;
    const int row0 = blockIdx.y * 128, col0 = bx * 128;

    int kbeg, kend;
    if (bx < 4)      { kbeg = 0; kend = 16; }
    else if (bx < 6) { kbeg = 0; kend = 8;  }
    else             { kbeg = 8; kend = 16; }

    auto copy_stage = [&](int st, int kc) {
        const int k0 = kc * BK;
        const bool hi = k0 >= 256;
        const int ka = hi ? k0 - 256 : k0;
        const __half* aP = hi ? hF : aggF;
        char* d = sm + st * STG3P;
#pragma unroll
        for (int i = 0; i < 6; i++) {
            const int idx = i * 256 + tid;
            if (idx < 512) {
                const int r = idx >> 2, j = idx & 3;
                cpasync16(d + r * (SA * 2) + j * 16,
                          aP + (size_t)(row0 + r) * KD + ka + j * 8);
            } else {
                const int rb = idx - 512;
                const int p = rb >> 9, rr = rb & 511;
                const int r = rr >> 2, j = rr & 3;
                const int c = col0 + r;
                const __half* W;
                if (hi) W = (p ? WhhL : WhhH)
                            + (size_t)((c < 768) ? c : c - 256) * KD + ka;
                else    W = (p ? WfL : WfH) + (size_t)c * KD + ka;
                cpasync16(d + (1 + p) * PLANEB + r * (SA * 2) + j * 16, W + j * 8);
            }
        }
        asm volatile("cp.async.commit_group;" ::: "memory");
    };

    ACC_INIT();
    copy_stage(0, kbeg);
    if (kbeg + 1 < kend) copy_stage(1, kbeg + 1);
    for (int c = kbeg; c < kend; c++) {
        if (c + 1 < kend) asm volatile("cp.async.wait_group 1;" ::: "memory");
        else              asm volatile("cp.async.wait_group 0;" ::: "memory");
        __syncthreads();
        if (c + 2 < kend) copy_stage((c + 2 - kbeg) % 3, c + 2);
        GEMM2P(sb + (uint32_t)(((c - kbeg) % 3) * STG3P));
    }
#pragma unroll
    for (int mi = 0; mi < 2; mi++) {
        const int r = row0 + wm * 32 + mi * 16 + g;
#pragma unroll
        for (int ni = 0; ni < 8; ni++) {
            const int cc = col0 + wn * 64 + ni * 8 + tq * 2;
            const float b0 = cbias[cc], b1 = cbias[cc + 1];
            *(float2*)(C + (size_t)r * 1024 + cc) =
                make_float2(acc[mi][ni][0] + b0, acc[mi][ni][1] + b1);
            *(float2*)(C + (size_t)(r + 8) * 1024 + cc) =
                make_float2(acc[mi][ni][2] + b0, acc[mi][ni][3] + b1);
        }
    }
}

// ---------------- prep kernels -----------------------------------------------
__global__ void prep_x(const float* __restrict__ x, __half* __restrict__ xf) {
    const int idx = blockIdx.x * 256 + threadIdx.x;
    if (idx >= NN * KD) return;
    const int row = idx >> 8, col = idx & 255;
    const float v = (row < NREAL && col < 200) ? x[row * 200 + col] : 0.0f;
    xf[idx] = __float2half(v);
}
__global__ void prep_wred(const float* __restrict__ W,
                          __half* __restrict__ wh, __half* __restrict__ wl) {
    const int idx = blockIdx.x * 256 + threadIdx.x;
    if (idx >= 256 * KD) return;
    const int n = idx >> 8, k = idx & 255;
    const float v = (k < 200) ? W[n * 200 + k] : 0.0f;
    split1h(v, wh[idx], wl[idx]);
}
__global__ void prep_split(const float* __restrict__ W, int n,
                           __half* __restrict__ wh, __half* __restrict__ wl) {
    const int idx = blockIdx.x * 256 + threadIdx.x;
    if (idx >= n) return;
    split1h(W[idx], wh[idx], wl[idx]);
}
__global__ void prep_cbias(const float* __restrict__ bih, const float* __restrict__ bhh,
                           float* __restrict__ cb) {
    const int c = blockIdx.x * 256 + threadIdx.x;
    if (c >= 1024) return;
    float v;
    if (c < 512)       v = bih[c] + bhh[c];
    else if (c < 768)  v = bih[c];
    else               v = bhh[c - 256];
    cb[c] = v;
}
__global__ void split_h(const float* __restrict__ h, __half* __restrict__ hf) {
    const int idx = blockIdx.x * 256 + threadIdx.x;
    if (idx >= NN * HID) return;
    hf[idx] = __float2half(h[idx]);
}

// ---------------- CSR build (parallel 3-phase scan) --------------------------
__global__ void hist_kernel(const int* __restrict__ ei, int* __restrict__ cnt) {
    const int e = blockIdx.x * 256 + threadIdx.x;
    if (e >= NE) return;
    atomicAdd(&cnt[ei[NE + e]], 1);
}
__global__ void scan_local(const int* __restrict__ cnt, int* __restrict__ rowptr,
                           int* __restrict__ bsum) {
    __shared__ int s[1024];
    const int tid = threadIdx.x;
    const int idx = blockIdx.x * 1024 + tid;
    int v = (idx < NN) ? cnt[idx] : 0;
    s[tid] = v;
    __syncthreads();
#pragma unroll
    for (int off = 1; off < 1024; off <<= 1) {
        int t = (tid >= off) ? s[tid - off] : 0;
        __syncthreads();
        s[tid] += t;
        __syncthreads();
    }
    if (idx < NN) rowptr[idx + 1] = s[tid];
    if (tid == 1023) bsum[blockIdx.x] = s[1023];
}
__global__ void scan_bsum(const int* __restrict__ bsum, int* __restrict__ boff) {
    if (threadIdx.x == 0) {
        int acc = 0;
        for (int i = 0; i < SCANB; i++) { boff[i] = acc; acc += bsum[i]; }
    }
}
__global__ void scan_add(int* __restrict__ rowptr, const int* __restrict__ boff) {
    const int idx = blockIdx.x * 1024 + threadIdx.x;
    if (idx == 0) rowptr[0] = 0;
    if (idx < NN) rowptr[idx + 1] += boff[blockIdx.x];
}
__global__ void copycur_kernel(const int* __restrict__ rowptr, int* __restrict__ cur) {
    const int i = blockIdx.x * 256 + threadIdx.x;
    if (i < NN) cur[i] = rowptr[i];
}
__global__ void fill_kernel(const int* __restrict__ ei, int* __restrict__ cur,
                            int* __restrict__ eidx) {
    const int e = blockIdx.x * 256 + threadIdx.x;
    if (e >= NE) return;
    const int pos = atomicAdd(&cur[ei[NE + e]], 1);
    eidx[pos] = ei[e];
}

// ---------------- aggregation: warp/dst-node gather of h -> fp16 plane -------
__global__ void agg_kernel(const float* __restrict__ h,
                           const int* __restrict__ rowptr, const int* __restrict__ eidx,
                           __half* __restrict__ aggF)
{
    const int w = (blockIdx.x * blockDim.x + threadIdx.x) >> 5;
    const int lane = threadIdx.x & 31;
    if (w >= NN) return;
    const int beg = rowptr[w], end = rowptr[w + 1];
    float4 a0 = make_float4(0, 0, 0, 0), a1 = make_float4(0, 0, 0, 0);
    for (int i = beg; i < end; i++) {
        const int s = eidx[i];
        const float4* hr = (const float4*)(h + (size_t)s * 256);
        const float4 v0 = hr[lane * 2], v1 = hr[lane * 2 + 1];
        a0.x += v0.x; a0.y += v0.y; a0.z += v0.z; a0.w += v0.w;
        a1.x += v1.x; a1.y += v1.y; a1.z += v1.z; a1.w += v1.w;
    }
    __half2 p0 = __floats2half2_rn(a0.x, a0.y);
    __half2 p1 = __floats2half2_rn(a0.z, a0.w);
    __half2 p2 = __floats2half2_rn(a1.x, a1.y);
    __half2 p3 = __floats2half2_rn(a1.z, a1.w);
    uint4 v;
    v.x = *(unsigned*)&p0; v.y = *(unsigned*)&p1;
    v.z = *(unsigned*)&p2; v.w = *(unsigned*)&p3;
    *(uint4*)(aggF + (size_t)w * 256 + lane * 8) = v;
}

// ---------------- fused GRU (reads pre-summed gates) -------------------------
__global__ void gru_kernel(const float* __restrict__ gates,
                           float* __restrict__ h, __half* __restrict__ hf)
{
    const int idx = blockIdx.x * blockDim.x + threadIdx.x;
    if (idx >= NN * 64) return;
    const int row = idx >> 6, c = (idx & 63) * 4;
    const float* G = gates + (size_t)row * 1024;
    const float4 rs = *(const float4*)(G + c);
    const float4 zs = *(const float4*)(G + 256 + c);
    const float4 iv = *(const float4*)(G + 512 + c);
    const float4 hv2 = *(const float4*)(G + 768 + c);
    float4* H = (float4*)(h + (size_t)row * 256 + c);
    const float4 hv = *H;

    float4 o;
    { float r = sigf(rs.x), z = sigf(zs.x);
      float n = tanhf(iv.x + r * hv2.x); o.x = (1.0f - z) * n + z * hv.x; }
    { float r = sigf(rs.y), z = sigf(zs.y);
      float n = tanhf(iv.y + r * hv2.y); o.y = (1.0f - z) * n + z * hv.y; }
    { float r = sigf(rs.z), z = sigf(zs.z);
      float n = tanhf(iv.z + r * hv2.z); o.z = (1.0f - z) * n + z * hv.z; }
    { float r = sigf(rs.w), z = sigf(zs.w);
      float n = tanhf(iv.w + r * hv2.w); o.w = (1.0f - z) * n + z * hv.w; }
    *H = o;

    __half2 p01 = __floats2half2_rn(o.x, o.y);
    __half2 p23 = __floats2half2_rn(o.z, o.w);
    uint2 v;
    v.x = *(unsigned*)&p01; v.y = *(unsigned*)&p23;
    *(uint2*)(hf + (size_t)row * 256 + c) = v;
}

// ---------------- head -------------------------------------------------------
__global__ void head_kernel(const float* __restrict__ h,
                            const float* __restrict__ W_lin,
                            const float* __restrict__ b_lin,
                            float* __restrict__ out, int N)
{
    const int gt = blockIdx.x * blockDim.x + threadIdx.x;
    const int node = gt >> 5;
    const int lane = gt & 31;
    if (node >= N) return;
    const float4* hr = (const float4*)(h + (size_t)node * HID);
    const float4* w0 = (const float4*)(W_lin);
    const float4* w1 = (const float4*)(W_lin + HID);
    float a0 = 0.0f, a1 = 0.0f;
#pragma unroll
    for (int it = 0; it < 2; it++) {
        const int i = lane + it * 32;
        float4 v = hr[i];
        v.x = fmaxf(v.x, 0.f); v.y = fmaxf(v.y, 0.f);
        v.z = fmaxf(v.z, 0.f); v.w = fmaxf(v.w, 0.f);
        const float4 x0 = w0[i], x1 = w1[i];
        a0 += v.x * x0.x + v.y * x0.y + v.z * x0.z + v.w * x0.w;
        a1 += v.x * x1.x + v.y * x1.y + v.z * x1.z + v.w * x1.w;
    }
#pragma unroll
    for (int off = 16; off > 0; off >>= 1) {
        a0 += __shfl_down_sync(0xffffffffu, a0, off);
        a1 += __shfl_down_sync(0xffffffffu, a1, off);
    }
    if (lane == 0) {
        const float o0 = a0 + b_lin[0];
        const float o1 = a1 + b_lin[1];
        const float mx = fmaxf(o0, o1);
        const float lse = mx + logf(expf(o0 - mx) + expf(o1 - mx));
        out[(size_t)node * 2 + 0] = o0 - lse;
        out[(size_t)node * 2 + 1] = o1 - lse;
    }
}

// ---------------- launch -----------------------------------------------------
extern "C" void kernel_launch(void* const* d_in, const int* in_sizes, int n_in,
                              void* d_out, int out_size)
{
    const float* x        = (const float*)d_in[0];
    const int*   ei       = (const int*)  d_in[1];
    const float* W_reduce = (const float*)d_in[3];
    const float* b_reduce = (const float*)d_in[4];
    const float* W_ggc    = (const float*)d_in[5];
    const float* W_ih     = (const float*)d_in[6];
    const float* W_hh     = (const float*)d_in[7];
    const float* b_ih     = (const float*)d_in[8];
    const float* b_hh     = (const float*)d_in[9];
    const float* W_lin    = (const float*)d_in[10];
    const float* b_lin    = (const float*)d_in[11];
    float* out = (float*)d_out;

    float *h, *gates, *cbias;
    __half *hF, *xF, *aggF, *WfH, *WfL, *WhH, *WhL, *WrH, *WrL, *WiH, *WiL, *WgH, *WgL;
    int *cnt, *rowptr, *cur, *eidx, *bsum, *boff;
    cudaGetSymbolAddress((void**)&h, g_h);
    cudaGetSymbolAddress((void**)&gates, g_gates);
    cudaGetSymbolAddress((void**)&cbias, g_cbias);
    cudaGetSymbolAddress((void**)&hF, g_hF);
    cudaGetSymbolAddress((void**)&xF, g_xF);
    cudaGetSymbolAddress((void**)&aggF, g_aggF);
    cudaGetSymbolAddress((void**)&WfH, g_WfusH);
    cudaGetSymbolAddress((void**)&WfL, g_WfusL);
    cudaGetSymbolAddress((void**)&WhH, g_WhhH);
    cudaGetSymbolAddress((void**)&WhL, g_WhhL);
    cudaGetSymbolAddress((void**)&WrH, g_WredH);
    cudaGetSymbolAddress((void**)&WrL, g_WredL);
    cudaGetSymbolAddress((void**)&WiH, g_WihH);
    cudaGetSymbolAddress((void**)&WiL, g_WihL);
    cudaGetSymbolAddress((void**)&WgH, g_WgH);
    cudaGetSymbolAddress((void**)&WgL, g_WgL);
    cudaGetSymbolAddress((void**)&cnt, g_cnt);
    cudaGetSymbolAddress((void**)&rowptr, g_rowptr);
    cudaGetSymbolAddress((void**)&cur, g_cur);
    cudaGetSymbolAddress((void**)&eidx, g_eidx);
    cudaGetSymbolAddress((void**)&bsum, g_bsum);
    cudaGetSymbolAddress((void**)&boff, g_boff);

    cudaFuncSetAttribute(gemm_init, cudaFuncAttributeMaxDynamicSharedMemorySize, GSMEM3);
    cudaFuncSetAttribute(gemm_step, cudaFuncAttributeMaxDynamicSharedMemorySize, GSMEM3);
    cudaFuncSetAttribute(gemm_wfus, cudaFuncAttributeMaxDynamicSharedMemorySize, GSMEM4);

    // ---- preprocessing ----
    prep_x<<<(NN * KD + 255) / 256, 256>>>(x, xF);
    prep_wred<<<(256 * KD + 255) / 256, 256>>>(W_reduce, WrH, WrL);
    prep_split<<<(768 * KD + 255) / 256, 256>>>(W_hh, 768 * KD, WhH, WhL);
    prep_split<<<(768 * KD + 255) / 256, 256>>>(W_ih, 768 * KD, WiH, WiL);
    prep_split<<<(NSTEP * 65536 + 255) / 256, 256>>>(W_ggc, NSTEP * 65536, WgH, WgL);
    gemm_wfus<<<dim3(2, 6, NSTEP), 256, GSMEM4>>>(WiH, WiL, WgH, WgL, WfH, WfL);
    prep_cbias<<<4, 256>>>(b_ih, b_hh, cbias);
    cudaMemsetAsync(cnt, 0, NN * sizeof(int));
    hist_kernel<<<(NE + 255) / 256, 256>>>(ei, cnt);
    scan_local<<<SCANB, 1024>>>(cnt, rowptr, bsum);
    scan_bsum<<<1, 32>>>(bsum, boff);
    scan_add<<<SCANB, 1024>>>(rowptr, boff);
    copycur_kernel<<<(NN + 255) / 256, 256>>>(rowptr, cur);
    fill_kernel<<<(NE + 255) / 256, 256>>>(ei, cur, eidx);

    const int MB = NN / 128;   // 391

    // h = x @ W_reduce^T + b_reduce
    gemm_init<<<dim3(2, MB), 256, GSMEM3>>>(xF, WrH, WrL, b_reduce, h, 256);
    split_h<<<(NN * HID + 255) / 256, 256>>>(h, hF);

    for (int t = 0; t < NSTEP; t++) {
        agg_kernel<<<(NN * 32 + 255) / 256, 256>>>(h, rowptr, eidx, aggF);
        gemm_step<<<dim3(8, MB), 256, GSMEM3>>>(
            aggF, hF,
            WfH + (size_t)t * 768 * KD, WfL + (size_t)t * 768 * KD,
            WhH, WhL, cbias, gates);
        gru_kernel<<<(NN * 64 + 255) / 256, 256>>>(gates, h, hF);
    }

    head_kernel<<<(NREAL * 32 + 255) / 256, 256>>>(h, W_lin, b_lin, out, NREAL);
}

// round 16
// speedup vs baseline: 2.4031x; 1.3847x over previous
#include <cuda_runtime.h>
#include <cuda_fp16.h>
#include <math.h>
#include <stdint.h>

#define NN      50048      // padded node count (391 * 128)
#define NREAL   50000
#define NE      300000
#define KD      256
#define HID     256
#define NSTEP   8
#define SCANB   ((NN + 1023) / 1024)   // 49

// ---------------- scratch (static device globals; no runtime alloc) ----------
__device__ float g_h    [NN * HID];
__device__ float g_gates[NN * 1024];       // [r_sum | z_sum | i_n | h_n]
__device__ __half g_hF[NN * KD];
__device__ __half g_xF[NN * KD];
__device__ __half g_aggF[NN * KD];
__device__ __half g_WfusF[NSTEP * 768 * KD];
__device__ __half g_WhhF[768 * KD];
__device__ __half g_WredF[256 * KD];
__device__ __half g_WihH[768 * KD], g_WihL[768 * KD];
__device__ __half g_WgH[NSTEP * 256 * 256], g_WgL[NSTEP * 256 * 256];
__device__ float g_cbias[1024];
__device__ int g_cnt[NN], g_rowptr[NN + 1], g_cur[NN], g_eidx[NE];
__device__ int g_bsum[SCANB], g_boff[SCANB];

// ---------------- shared GEMM machinery --------------------------------------
#define BK    32
#define SA    40                       // smem row stride in fp16 elems (80B)
#define PLANEB (128 * SA * 2)          // 10240 B
#define STG1P  (2 * PLANEB)            // 20480 B (1-product stage: A, B)
#define GSMEM1 (3 * STG1P)             // 61440 B (3 stages)
#define STG4P  (4 * PLANEB)            // 40960 B (3-product stage, wfus)
#define GSMEM4 (2 * STG4P)             // 81920 B

__device__ __forceinline__ void mma_f16(float* c, const unsigned* a, const unsigned* b)
{
    asm volatile(
        "mma.sync.aligned.m16n8k16.row.col.f32.f16.f16.f32 "
        "{%0,%1,%2,%3}, {%4,%5,%6,%7}, {%8,%9}, {%0,%1,%2,%3};\n"
        : "+f"(c[0]), "+f"(c[1]), "+f"(c[2]), "+f"(c[3])
        : "r"(a[0]), "r"(a[1]), "r"(a[2]), "r"(a[3]), "r"(b[0]), "r"(b[1]));
}
__device__ __forceinline__ void ldsm4(unsigned* r, uint32_t addr)
{
    asm volatile("ldmatrix.sync.aligned.m8n8.x4.shared.b16 {%0,%1,%2,%3}, [%4];"
                 : "=r"(r[0]), "=r"(r[1]), "=r"(r[2]), "=r"(r[3]) : "r"(addr));
}
__device__ __forceinline__ void cpasync16(char* dst, const void* src)
{
    asm volatile("cp.async.cg.shared.global [%0], [%1], 16;"
                 :: "l"((uint64_t)__cvta_generic_to_shared(dst)), "l"(src) : "memory");
}

// 1-product compute: C += A*B.  Planes: A@0, B@PLANEB.
#define GEMM1P(base)                                                           \
    do {                                                                       \
        _Pragma("unroll")                                                      \
        for (int ks = 0; ks < 2; ks++) {                                       \
            const uint32_t kso = ks * 32;                                      \
            unsigned aF[2][4];                                                 \
            ldsm4(aF[0], (base) + aoffH0 + kso);                               \
            ldsm4(aF[1], (base) + aoffH1 + kso);                               \
            _Pragma("unroll")                                                  \
            for (int ni2 = 0; ni2 < 8; ni2 += 2) {                             \
                unsigned bF[4];                                                \
                const uint32_t bo = boff0 + (uint32_t)(ni2 * 8 * SA * 2) + kso;\
                ldsm4(bF, (base) + PLANEB + bo);                               \
                _Pragma("unroll")                                              \
                for (int mi = 0; mi < 2; mi++)                                 \
                    _Pragma("unroll")                                          \
                    for (int q = 0; q < 2; q++)                                \
                        mma_f16(acc[mi][ni2 + q], aF[mi], bF + q * 2);         \
            }                                                                  \
        }                                                                      \
    } while (0)

// 3-product compute (wfus only): planes Ah@0, Al@1, Bh@2, Bl@3.
#define GEMM3P(base)                                                           \
    do {                                                                       \
        _Pragma("unroll")                                                      \
        for (int ks = 0; ks < 2; ks++) {                                       \
            const uint32_t kso = ks * 32;                                      \
            unsigned aH[2][4], aL[2][4];                                       \
            ldsm4(aH[0], (base) + 0 * PLANEB + aoffH0 + kso);                  \
            ldsm4(aH[1], (base) + 0 * PLANEB + aoffH1 + kso);                  \
            ldsm4(aL[0], (base) + 1 * PLANEB + aoffH0 + kso);                  \
            ldsm4(aL[1], (base) + 1 * PLANEB + aoffH1 + kso);                  \
            _Pragma("unroll")                                                  \
            for (int ni2 = 0; ni2 < 8; ni2 += 2) {                             \
                unsigned bH[4], bL[4];                                         \
                const uint32_t bo = boff0 + (uint32_t)(ni2 * 8 * SA * 2) + kso;\
                ldsm4(bH, (base) + 2 * PLANEB + bo);                           \
                ldsm4(bL, (base) + 3 * PLANEB + bo);                           \
                _Pragma("unroll")                                              \
                for (int mi = 0; mi < 2; mi++)                                 \
                    _Pragma("unroll")                                          \
                    for (int q = 0; q < 2; q++)                                \
                        mma_f16(acc[mi][ni2 + q], aH[mi], bH + q * 2);         \
                _Pragma("unroll")                                              \
                for (int mi = 0; mi < 2; mi++)                                 \
                    _Pragma("unroll")                                          \
                    for (int q = 0; q < 2; q++)                                \
                        mma_f16(acc[mi][ni2 + q], aH[mi], bL + q * 2);         \
                _Pragma("unroll")                                              \
                for (int mi = 0; mi < 2; mi++)                                 \
                    _Pragma("unroll")                                          \
                    for (int q = 0; q < 2; q++)                                \
                        mma_f16(acc[mi][ni2 + q], aL[mi], bH + q * 2);         \
            }                                                                  \
        }                                                                      \
    } while (0)

#define FRAG_SETUP()                                                           \
    const int tid  = threadIdx.x;                                              \
    const int lane = tid & 31;                                                 \
    const int warp = tid >> 5;                                                 \
    const int wm   = warp & 3;                                                 \
    const int wn   = warp >> 2;                                                \
    const int g    = lane >> 2;                                                \
    const int tq   = lane & 3;                                                 \
    const int a_row = wm * 32 + (lane & 15);                                   \
    const int a_kx  = (lane >> 4) * 16;                                        \
    const uint32_t aoffH0 = (uint32_t)(a_row * SA * 2 + a_kx);                 \
    const uint32_t aoffH1 = aoffH0 + 16 * SA * 2;                              \
    const int b_col = wn * 64 + (lane & 7) + ((lane >> 4) & 1) * 8;            \
    const int b_kx  = ((lane >> 3) & 1) * 16;                                  \
    const uint32_t boff0 = (uint32_t)(b_col * SA * 2 + b_kx)

#define ACC_INIT()                                                             \
    float acc[2][8][4];                                                        \
    _Pragma("unroll")                                                          \
    for (int mi = 0; mi < 2; mi++)                                             \
        _Pragma("unroll")                                                      \
        for (int ni = 0; ni < 8; ni++)                                         \
            _Pragma("unroll")                                                  \
            for (int j = 0; j < 4; j++) acc[mi][ni][j] = 0.0f

__device__ __forceinline__ void split1h(float v, __half& h, __half& l) {
    h = __float2half(v);
    l = __float2half(v - __half2float(h));
}
__device__ __forceinline__ float sigf(float x) { return 1.0f / (1.0f + __expf(-x)); }

// ---------------- init GEMM: h = xF @ WredF^T + bias -------------------------
__global__ void __launch_bounds__(256, 2)
gemm_init(const __half* __restrict__ AF, const __half* __restrict__ BF,
          const float* __restrict__ bias, float* __restrict__ C, int ldc)
{
    extern __shared__ char sm[];
    const uint32_t sb = (uint32_t)__cvta_generic_to_shared(sm);
    FRAG_SETUP();
    const int row0 = blockIdx.y * 128, col0 = blockIdx.x * 128;

    auto copy_stage = [&](int st, int kc) {
        const int k0 = kc * BK;
        char* d = sm + st * STG1P;
#pragma unroll
        for (int i = 0; i < 4; i++) {
            const int idx = i * 256 + tid;             // 0..1023
            const int p = idx >> 9;                    // 0=A, 1=B
            const int rr = idx & 511;
            const int r = rr >> 2, j = rr & 3;
            const __half* src = p ? (BF + (size_t)(col0 + r) * KD + k0 + j * 8)
                                  : (AF + (size_t)(row0 + r) * KD + k0 + j * 8);
            cpasync16(d + p * PLANEB + r * (SA * 2) + j * 16, src);
        }
        asm volatile("cp.async.commit_group;" ::: "memory");
    };

    ACC_INIT();
    const int NC = KD / BK;
    copy_stage(0, 0);
    copy_stage(1, 1);
    for (int c = 0; c < NC; c++) {
        if (c + 1 < NC) asm volatile("cp.async.wait_group 1;" ::: "memory");
        else            asm volatile("cp.async.wait_group 0;" ::: "memory");
        __syncthreads();
        if (c + 2 < NC) copy_stage((c + 2) % 3, c + 2);
        GEMM1P(sb + (uint32_t)((c % 3) * STG1P));
    }
#pragma unroll
    for (int mi = 0; mi < 2; mi++) {
        const int r = row0 + wm * 32 + mi * 16 + g;
#pragma unroll
        for (int ni = 0; ni < 8; ni++) {
            const int cc = col0 + wn * 64 + ni * 8 + tq * 2;
            const float b0 = bias[cc], b1 = bias[cc + 1];
            *(float2*)(C + (size_t)r * ldc + cc) =
                make_float2(acc[mi][ni][0] + b0, acc[mi][ni][1] + b1);
            *(float2*)(C + (size_t)(r + 8) * ldc + cc) =
                make_float2(acc[mi][ni][2] + b0, acc[mi][ni][3] + b1);
        }
    }
}

// ---------------- Wfused GEMM (3-product fp16) -> single fp16 plane ----------
__global__ void __launch_bounds__(256, 2)
gemm_wfus(const __half* __restrict__ AH, const __half* __restrict__ AL,
          const __half* __restrict__ BHall, const __half* __restrict__ BLall,
          __half* __restrict__ fF)
{
    extern __shared__ char sm[];
    const uint32_t sb = (uint32_t)__cvta_generic_to_shared(sm);
    FRAG_SETUP();
    const int row0 = blockIdx.y * 128, col0 = blockIdx.x * 128;
    const int t = blockIdx.z;
    const __half* gp[4] = {AH, AL, BHall + (size_t)t * 65536,
                           BLall + (size_t)t * 65536};

    auto copy_stage = [&](int st, int kc) {
        const int k0 = kc * BK;
        char* dst0 = sm + st * STG4P;
#pragma unroll
        for (int i = 0; i < 8; i++) {
            const int idx = i * 256 + tid;
            const int p = idx >> 9, r = (idx >> 2) & 127, j = idx & 3;
            const int grow = ((p < 2) ? row0 : col0) + r;
            cpasync16(dst0 + p * PLANEB + r * (SA * 2) + j * 16,
                      gp[p] + (size_t)grow * 256 + k0 + j * 8);
        }
        asm volatile("cp.async.commit_group;" ::: "memory");
    };

    ACC_INIT();
    copy_stage(0, 0);
    for (int c = 0; c < 8; c++) {
        asm volatile("cp.async.wait_group 0;" ::: "memory");
        __syncthreads();
        if (c + 1 < 8) copy_stage((c + 1) & 1, c + 1);
        GEMM3P(sb + (c & 1) * STG4P);
    }
    const size_t tb = (size_t)t * 768 * KD;
#pragma unroll
    for (int mi = 0; mi < 2; mi++) {
        const int r = row0 + wm * 32 + mi * 16 + g;
#pragma unroll
        for (int ni = 0; ni < 8; ni++) {
            const int cc = col0 + wn * 64 + ni * 8 + tq * 2;
#pragma unroll
            for (int j = 0; j < 4; j++) {
                const int o  = (j < 2) ? r : r + 8;
                const int kk = cc + (j & 1);
                fF[tb + (size_t)o * KD + kk] = __float2half(acc[mi][ni][j]);
            }
        }
    }
}

// ---------------- step GEMM: gates = [aggF|hF] @ B'^T + cbias ----------------
__global__ void __launch_bounds__(256, 2)
gemm_step(const __half* __restrict__ aggF, const __half* __restrict__ hF,
          const __half* __restrict__ WfF, const __half* __restrict__ WhhF,
          const float* __restrict__ cbias, float* __restrict__ C)
{
    extern __shared__ char sm[];
    const uint32_t sb = (uint32_t)__cvta_generic_to_shared(sm);
    FRAG_SETUP();
    const int bx   = blockIdx.x;
    const int row0 = blockIdx.y * 128, col0 = bx * 128;

    int kbeg, kend;
    if (bx < 4)      { kbeg = 0; kend = 16; }
    else if (bx < 6) { kbeg = 0; kend = 8;  }
    else             { kbeg = 8; kend = 16; }

    auto copy_stage = [&](int st, int kc) {
        const int k0 = kc * BK;
        const bool hi = k0 >= 256;
        const int ka = hi ? k0 - 256 : k0;
        const __half* aP = hi ? hF : aggF;
        char* d = sm + st * STG1P;
#pragma unroll
        for (int i = 0; i < 4; i++) {
            const int idx = i * 256 + tid;
            const int p = idx >> 9;
            const int rr = idx & 511;
            const int r = rr >> 2, j = rr & 3;
            const __half* src;
            if (p == 0) {
                src = aP + (size_t)(row0 + r) * KD + ka + j * 8;
            } else {
                const int c = col0 + r;
                if (hi) src = WhhF + (size_t)((c < 768) ? c : c - 256) * KD + ka + j * 8;
                else    src = WfF + (size_t)c * KD + ka + j * 8;
            }
            cpasync16(d + p * PLANEB + r * (SA * 2) + j * 16, src);
        }
        asm volatile("cp.async.commit_group;" ::: "memory");
    };

    ACC_INIT();
    copy_stage(0, kbeg);
    if (kbeg + 1 < kend) copy_stage(1, kbeg + 1);
    for (int c = kbeg; c < kend; c++) {
        if (c + 1 < kend) asm volatile("cp.async.wait_group 1;" ::: "memory");
        else              asm volatile("cp.async.wait_group 0;" ::: "memory");
        __syncthreads();
        if (c + 2 < kend) copy_stage((c + 2 - kbeg) % 3, c + 2);
        GEMM1P(sb + (uint32_t)(((c - kbeg) % 3) * STG1P));
    }
#pragma unroll
    for (int mi = 0; mi < 2; mi++) {
        const int r = row0 + wm * 32 + mi * 16 + g;
#pragma unroll
        for (int ni = 0; ni < 8; ni++) {
            const int cc = col0 + wn * 64 + ni * 8 + tq * 2;
            const float b0 = cbias[cc], b1 = cbias[cc + 1];
            *(float2*)(C + (size_t)r * 1024 + cc) =
                make_float2(acc[mi][ni][0] + b0, acc[mi][ni][1] + b1);
            *(float2*)(C + (size_t)(r + 8) * 1024 + cc) =
                make_float2(acc[mi][ni][2] + b0, acc[mi][ni][3] + b1);
        }
    }
}

// ---------------- prep kernels -----------------------------------------------
__global__ void prep_x(const float* __restrict__ x, __half* __restrict__ xf) {
    const int idx = blockIdx.x * 256 + threadIdx.x;
    if (idx >= NN * KD) return;
    const int row = idx >> 8, col = idx & 255;
    const float v = (row < NREAL && col < 200) ? x[row * 200 + col] : 0.0f;
    xf[idx] = __float2half(v);
}
__global__ void prep_wred(const float* __restrict__ W, __half* __restrict__ wf) {
    const int idx = blockIdx.x * 256 + threadIdx.x;
    if (idx >= 256 * KD) return;
    const int n = idx >> 8, k = idx & 255;
    const float v = (k < 200) ? W[n * 200 + k] : 0.0f;
    wf[idx] = __float2half(v);
}
__global__ void prep_single(const float* __restrict__ W, int n, __half* __restrict__ wf) {
    const int idx = blockIdx.x * 256 + threadIdx.x;
    if (idx >= n) return;
    wf[idx] = __float2half(W[idx]);
}
__global__ void prep_split(const float* __restrict__ W, int n,
                           __half* __restrict__ wh, __half* __restrict__ wl) {
    const int idx = blockIdx.x * 256 + threadIdx.x;
    if (idx >= n) return;
    split1h(W[idx], wh[idx], wl[idx]);
}
__global__ void prep_cbias(const float* __restrict__ bih, const float* __restrict__ bhh,
                           float* __restrict__ cb) {
    const int c = blockIdx.x * 256 + threadIdx.x;
    if (c >= 1024) return;
    float v;
    if (c < 512)       v = bih[c] + bhh[c];
    else if (c < 768)  v = bih[c];
    else               v = bhh[c - 256];
    cb[c] = v;
}
__global__ void split_h(const float* __restrict__ h, __half* __restrict__ hf) {
    const int idx = blockIdx.x * 256 + threadIdx.x;
    if (idx >= NN * HID) return;
    hf[idx] = __float2half(h[idx]);
}

// ---------------- CSR build (parallel 3-phase scan) --------------------------
__global__ void hist_kernel(const int* __restrict__ ei, int* __restrict__ cnt) {
    const int e = blockIdx.x * 256 + threadIdx.x;
    if (e >= NE) return;
    atomicAdd(&cnt[ei[NE + e]], 1);
}
__global__ void scan_local(const int* __restrict__ cnt, int* __restrict__ rowptr,
                           int* __restrict__ bsum) {
    __shared__ int s[1024];
    const int tid = threadIdx.x;
    const int idx = blockIdx.x * 1024 + tid;
    int v = (idx < NN) ? cnt[idx] : 0;
    s[tid] = v;
    __syncthreads();
#pragma unroll
    for (int off = 1; off < 1024; off <<= 1) {
        int t = (tid >= off) ? s[tid - off] : 0;
        __syncthreads();
        s[tid] += t;
        __syncthreads();
    }
    if (idx < NN) rowptr[idx + 1] = s[tid];
    if (tid == 1023) bsum[blockIdx.x] = s[1023];
}
__global__ void scan_bsum(const int* __restrict__ bsum, int* __restrict__ boff) {
    if (threadIdx.x == 0) {
        int acc = 0;
        for (int i = 0; i < SCANB; i++) { boff[i] = acc; acc += bsum[i]; }
    }
}
__global__ void scan_add(int* __restrict__ rowptr, const int* __restrict__ boff) {
    const int idx = blockIdx.x * 1024 + threadIdx.x;
    if (idx == 0) rowptr[0] = 0;
    if (idx < NN) rowptr[idx + 1] += boff[blockIdx.x];
}
__global__ void copycur_kernel(const int* __restrict__ rowptr, int* __restrict__ cur) {
    const int i = blockIdx.x * 256 + threadIdx.x;
    if (i < NN) cur[i] = rowptr[i];
}
__global__ void fill_kernel(const int* __restrict__ ei, int* __restrict__ cur,
                            int* __restrict__ eidx) {
    const int e = blockIdx.x * 256 + threadIdx.x;
    if (e >= NE) return;
    const int pos = atomicAdd(&cur[ei[NE + e]], 1);
    eidx[pos] = ei[e];
}

// ---------------- aggregation: warp/dst-node gather of h -> fp16 plane -------
__global__ void agg_kernel(const float* __restrict__ h,
                           const int* __restrict__ rowptr, const int* __restrict__ eidx,
                           __half* __restrict__ aggF)
{
    const int w = (blockIdx.x * blockDim.x + threadIdx.x) >> 5;
    const int lane = threadIdx.x & 31;
    if (w >= NN) return;
    const int beg = rowptr[w], end = rowptr[w + 1];
    float4 a0 = make_float4(0, 0, 0, 0), a1 = make_float4(0, 0, 0, 0);
    for (int i = beg; i < end; i++) {
        const int s = eidx[i];
        const float4* hr = (const float4*)(h + (size_t)s * 256);
        const float4 v0 = hr[lane * 2], v1 = hr[lane * 2 + 1];
        a0.x += v0.x; a0.y += v0.y; a0.z += v0.z; a0.w += v0.w;
        a1.x += v1.x; a1.y += v1.y; a1.z += v1.z; a1.w += v1.w;
    }
    __half2 p0 = __floats2half2_rn(a0.x, a0.y);
    __half2 p1 = __floats2half2_rn(a0.z, a0.w);
    __half2 p2 = __floats2half2_rn(a1.x, a1.y);
    __half2 p3 = __floats2half2_rn(a1.z, a1.w);
    uint4 v;
    v.x = *(unsigned*)&p0; v.y = *(unsigned*)&p1;
    v.z = *(unsigned*)&p2; v.w = *(unsigned*)&p3;
    *(uint4*)(aggF + (size_t)w * 256 + lane * 8) = v;
}

// ---------------- fused GRU (reads pre-summed gates) -------------------------
__global__ void gru_kernel(const float* __restrict__ gates,
                           float* __restrict__ h, __half* __restrict__ hf)
{
    const int idx = blockIdx.x * blockDim.x + threadIdx.x;
    if (idx >= NN * 64) return;
    const int row = idx >> 6, c = (idx & 63) * 4;
    const float* G = gates + (size_t)row * 1024;
    const float4 rs = *(const float4*)(G + c);
    const float4 zs = *(const float4*)(G + 256 + c);
    const float4 iv = *(const float4*)(G + 512 + c);
    const float4 hv2 = *(const float4*)(G + 768 + c);
    float4* H = (float4*)(h + (size_t)row * 256 + c);
    const float4 hv = *H;

    float4 o;
    { float r = sigf(rs.x), z = sigf(zs.x);
      float n = tanhf(iv.x + r * hv2.x); o.x = (1.0f - z) * n + z * hv.x; }
    { float r = sigf(rs.y), z = sigf(zs.y);
      float n = tanhf(iv.y + r * hv2.y); o.y = (1.0f - z) * n + z * hv.y; }
    { float r = sigf(rs.z), z = sigf(zs.z);
      float n = tanhf(iv.z + r * hv2.z); o.z = (1.0f - z) * n + z * hv.z; }
    { float r = sigf(rs.w), z = sigf(zs.w);
      float n = tanhf(iv.w + r * hv2.w); o.w = (1.0f - z) * n + z * hv.w; }
    *H = o;

    __half2 p01 = __floats2half2_rn(o.x, o.y);
    __half2 p23 = __floats2half2_rn(o.z, o.w);
    uint2 v;
    v.x = *(unsigned*)&p01; v.y = *(unsigned*)&p23;
    *(uint2*)(hf + (size_t)row * 256 + c) = v;
}

// ---------------- head -------------------------------------------------------
__global__ void head_kernel(const float* __restrict__ h,
                            const float* __restrict__ W_lin,
                            const float* __restrict__ b_lin,
                            float* __restrict__ out, int N)
{
    const int gt = blockIdx.x * blockDim.x + threadIdx.x;
    const int node = gt >> 5;
    const int lane = gt & 31;
    if (node >= N) return;
    const float4* hr = (const float4*)(h + (size_t)node * HID);
    const float4* w0 = (const float4*)(W_lin);
    const float4* w1 = (const float4*)(W_lin + HID);
    float a0 = 0.0f, a1 = 0.0f;
#pragma unroll
    for (int it = 0; it < 2; it++) {
        const int i = lane + it * 32;
        float4 v = hr[i];
        v.x = fmaxf(v.x, 0.f); v.y = fmaxf(v.y, 0.f);
        v.z = fmaxf(v.z, 0.f); v.w = fmaxf(v.w, 0.f);
        const float4 x0 = w0[i], x1 = w1[i];
        a0 += v.x * x0.x + v.y * x0.y + v.z * x0.z + v.w * x0.w;
        a1 += v.x * x1.x + v.y * x1.y + v.z * x1.z + v.w * x1.w;
    }
#pragma unroll
    for (int off = 16; off > 0; off >>= 1) {
        a0 += __shfl_down_sync(0xffffffffu, a0, off);
        a1 += __shfl_down_sync(0xffffffffu, a1, off);
    }
    if (lane == 0) {
        const float o0 = a0 + b_lin[0];
        const float o1 = a1 + b_lin[1];
        const float mx = fmaxf(o0, o1);
        const float lse = mx + logf(expf(o0 - mx) + expf(o1 - mx));
        out[(size_t)node * 2 + 0] = o0 - lse;
        out[(size_t)node * 2 + 1] = o1 - lse;
    }
}

// ---------------- launch -----------------------------------------------------
extern "C" void kernel_launch(void* const* d_in, const int* in_sizes, int n_in,
                              void* d_out, int out_size)
{
    const float* x        = (const float*)d_in[0];
    const int*   ei       = (const int*)  d_in[1];
    const float* W_reduce = (const float*)d_in[3];
    const float* b_reduce = (const float*)d_in[4];
    const float* W_ggc    = (const float*)d_in[5];
    const float* W_ih     = (const float*)d_in[6];
    const float* W_hh     = (const float*)d_in[7];
    const float* b_ih     = (const float*)d_in[8];
    const float* b_hh     = (const float*)d_in[9];
    const float* W_lin    = (const float*)d_in[10];
    const float* b_lin    = (const float*)d_in[11];
    float* out = (float*)d_out;

    float *h, *gates, *cbias;
    __half *hF, *xF, *aggF, *WfF, *WhhF, *WrF, *WiH, *WiL, *WgH, *WgL;
    int *cnt, *rowptr, *cur, *eidx, *bsum, *boff;
    cudaGetSymbolAddress((void**)&h, g_h);
    cudaGetSymbolAddress((void**)&gates, g_gates);
    cudaGetSymbolAddress((void**)&cbias, g_cbias);
    cudaGetSymbolAddress((void**)&hF, g_hF);
    cudaGetSymbolAddress((void**)&xF, g_xF);
    cudaGetSymbolAddress((void**)&aggF, g_aggF);
    cudaGetSymbolAddress((void**)&WfF, g_WfusF);
    cudaGetSymbolAddress((void**)&WhhF, g_WhhF);
    cudaGetSymbolAddress((void**)&WrF, g_WredF);
    cudaGetSymbolAddress((void**)&WiH, g_WihH);
    cudaGetSymbolAddress((void**)&WiL, g_WihL);
    cudaGetSymbolAddress((void**)&WgH, g_WgH);
    cudaGetSymbolAddress((void**)&WgL, g_WgL);
    cudaGetSymbolAddress((void**)&cnt, g_cnt);
    cudaGetSymbolAddress((void**)&rowptr, g_rowptr);
    cudaGetSymbolAddress((void**)&cur, g_cur);
    cudaGetSymbolAddress((void**)&eidx, g_eidx);
    cudaGetSymbolAddress((void**)&bsum, g_bsum);
    cudaGetSymbolAddress((void**)&boff, g_boff);

    cudaFuncSetAttribute(gemm_init, cudaFuncAttributeMaxDynamicSharedMemorySize, GSMEM1);
    cudaFuncSetAttribute(gemm_step, cudaFuncAttributeMaxDynamicSharedMemorySize, GSMEM1);
    cudaFuncSetAttribute(gemm_wfus, cudaFuncAttributeMaxDynamicSharedMemorySize, GSMEM4);

    // ---- preprocessing ----
    prep_x<<<(NN * KD + 255) / 256, 256>>>(x, xF);
    prep_wred<<<(256 * KD + 255) / 256, 256>>>(W_reduce, WrF);
    prep_single<<<(768 * KD + 255) / 256, 256>>>(W_hh, 768 * KD, WhhF);
    prep_split<<<(768 * KD + 255) / 256, 256>>>(W_ih, 768 * KD, WiH, WiL);
    prep_split<<<(NSTEP * 65536 + 255) / 256, 256>>>(W_ggc, NSTEP * 65536, WgH, WgL);
    gemm_wfus<<<dim3(2, 6, NSTEP), 256, GSMEM4>>>(WiH, WiL, WgH, WgL, WfF);
    prep_cbias<<<4, 256>>>(b_ih, b_hh, cbias);
    cudaMemsetAsync(cnt, 0, NN * sizeof(int));
    hist_kernel<<<(NE + 255) / 256, 256>>>(ei, cnt);
    scan_local<<<SCANB, 1024>>>(cnt, rowptr, bsum);
    scan_bsum<<<1, 32>>>(bsum, boff);
    scan_add<<<SCANB, 1024>>>(rowptr, boff);
    copycur_kernel<<<(NN + 255) / 256, 256>>>(rowptr, cur);
    fill_kernel<<<(NE + 255) / 256, 256>>>(ei, cur, eidx);

    const int MB = NN / 128;   // 391

    // h = x @ W_reduce^T + b_reduce
    gemm_init<<<dim3(2, MB), 256, GSMEM1>>>(xF, WrF, b_reduce, h, 256);
    split_h<<<(NN * HID + 255) / 256, 256>>>(h, hF);

    for (int t = 0; t < NSTEP; t++) {
        agg_kernel<<<(NN * 32 + 255) / 256, 256>>>(h, rowptr, eidx, aggF);
        gemm_step<<<dim3(8, MB), 256, GSMEM1>>>(
            aggF, hF, WfF + (size_t)t * 768 * KD, WhhF, cbias, gates);
        gru_kernel<<<(NN * 64 + 255) / 256, 256>>>(gates, h, hF);
    }

    head_kernel<<<(NREAL * 32 + 255) / 256, 256>>>(h, W_lin, b_lin, out, NREAL);
}

// round 17
// speedup vs baseline: 2.6863x; 1.1178x over previous
#include <cuda_runtime.h>
#include <cuda_fp16.h>
#include <math.h>
#include <stdint.h>

#define NN      50048      // padded node count (391 * 128)
#define NREAL   50000
#define NE      300000
#define KD      256
#define HID     256
#define NSTEP   8
#define SCANB   ((NN + 1023) / 1024)   // 49

// ---------------- scratch (static device globals; no runtime alloc) ----------
__device__ float  g_h    [NN * HID];
__device__ __half g_gates[NN * 1024];      // [r_sum | z_sum | i_n | h_n] fp16
__device__ __half g_hF[NN * KD];
__device__ __half g_xF[NN * KD];
__device__ __half g_aggF[NN * KD];
__device__ __half g_WfusF[NSTEP * 768 * KD];
__device__ __half g_WhhF[768 * KD];
__device__ __half g_WredF[256 * KD];
__device__ __half g_WihH[768 * KD], g_WihL[768 * KD];
__device__ __half g_WgH[NSTEP * 256 * 256], g_WgL[NSTEP * 256 * 256];
__device__ float g_cbias[1024];
__device__ int g_cnt[NN], g_rowptr[NN + 1], g_cur[NN], g_eidx[NE];
__device__ int g_bsum[SCANB], g_boff[SCANB];

// ---------------- shared GEMM machinery --------------------------------------
#define BK    32
#define SA    40                       // smem row stride in fp16 elems (80B)
#define PLANEB (128 * SA * 2)          // 10240 B
#define STG1P  (2 * PLANEB)            // 20480 B (1-product stage: A, B)
#define GSMEM1 (3 * STG1P)             // 61440 B (3 stages)
#define STG4P  (4 * PLANEB)            // 40960 B (3-product stage, wfus)
#define GSMEM4 (2 * STG4P)             // 81920 B

__device__ __forceinline__ void mma_f16(float* c, const unsigned* a, const unsigned* b)
{
    asm volatile(
        "mma.sync.aligned.m16n8k16.row.col.f32.f16.f16.f32 "
        "{%0,%1,%2,%3}, {%4,%5,%6,%7}, {%8,%9}, {%0,%1,%2,%3};\n"
        : "+f"(c[0]), "+f"(c[1]), "+f"(c[2]), "+f"(c[3])
        : "r"(a[0]), "r"(a[1]), "r"(a[2]), "r"(a[3]), "r"(b[0]), "r"(b[1]));
}
__device__ __forceinline__ void ldsm4(unsigned* r, uint32_t addr)
{
    asm volatile("ldmatrix.sync.aligned.m8n8.x4.shared.b16 {%0,%1,%2,%3}, [%4];"
                 : "=r"(r[0]), "=r"(r[1]), "=r"(r[2]), "=r"(r[3]) : "r"(addr));
}
__device__ __forceinline__ void cpasync16(char* dst, const void* src)
{
    asm volatile("cp.async.cg.shared.global [%0], [%1], 16;"
                 :: "l"((uint64_t)__cvta_generic_to_shared(dst)), "l"(src) : "memory");
}

// 1-product compute: C += A*B.  Planes: A@0, B@PLANEB.
#define GEMM1P(base)                                                           \
    do {                                                                       \
        _Pragma("unroll")                                                      \
        for (int ks = 0; ks < 2; ks++) {                                       \
            const uint32_t kso = ks * 32;                                      \
            unsigned aF[2][4];                                                 \
            ldsm4(aF[0], (base) + aoffH0 + kso);                               \
            ldsm4(aF[1], (base) + aoffH1 + kso);                               \
            _Pragma("unroll")                                                  \
            for (int ni2 = 0; ni2 < 8; ni2 += 2) {                             \
                unsigned bF[4];                                                \
                const uint32_t bo = boff0 + (uint32_t)(ni2 * 8 * SA * 2) + kso;\
                ldsm4(bF, (base) + PLANEB + bo);                               \
                _Pragma("unroll")                                              \
                for (int mi = 0; mi < 2; mi++)                                 \
                    _Pragma("unroll")                                          \
                    for (int q = 0; q < 2; q++)                                \
                        mma_f16(acc[mi][ni2 + q], aF[mi], bF + q * 2);         \
            }                                                                  \
        }                                                                      \
    } while (0)

// 3-product compute (wfus only): planes Ah@0, Al@1, Bh@2, Bl@3.
#define GEMM3P(base)                                                           \
    do {                                                                       \
        _Pragma("unroll")                                                      \
        for (int ks = 0; ks < 2; ks++) {                                       \
            const uint32_t kso = ks * 32;                                      \
            unsigned aH[2][4], aL[2][4];                                       \
            ldsm4(aH[0], (base) + 0 * PLANEB + aoffH0 + kso);                  \
            ldsm4(aH[1], (base) + 0 * PLANEB + aoffH1 + kso);                  \
            ldsm4(aL[0], (base) + 1 * PLANEB + aoffH0 + kso);                  \
            ldsm4(aL[1], (base) + 1 * PLANEB + aoffH1 + kso);                  \
            _Pragma("unroll")                                                  \
            for (int ni2 = 0; ni2 < 8; ni2 += 2) {                             \
                unsigned bH[4], bL[4];                                         \
                const uint32_t bo = boff0 + (uint32_t)(ni2 * 8 * SA * 2) + kso;\
                ldsm4(bH, (base) + 2 * PLANEB + bo);                           \
                ldsm4(bL, (base) + 3 * PLANEB + bo);                           \
                _Pragma("unroll")                                              \
                for (int mi = 0; mi < 2; mi++)                                 \
                    _Pragma("unroll")                                          \
                    for (int q = 0; q < 2; q++)                                \
                        mma_f16(acc[mi][ni2 + q], aH[mi], bH + q * 2);         \
                _Pragma("unroll")                                              \
                for (int mi = 0; mi < 2; mi++)                                 \
                    _Pragma("unroll")                                          \
                    for (int q = 0; q < 2; q++)                                \
                        mma_f16(acc[mi][ni2 + q], aH[mi], bL + q * 2);         \
                _Pragma("unroll")                                              \
                for (int mi = 0; mi < 2; mi++)                                 \
                    _Pragma("unroll")                                          \
                    for (int q = 0; q < 2; q++)                                \
                        mma_f16(acc[mi][ni2 + q], aL[mi], bH + q * 2);         \
            }                                                                  \
        }                                                                      \
    } while (0)

#define FRAG_SETUP()                                                           \
    const int tid  = threadIdx.x;                                              \
    const int lane = tid & 31;                                                 \
    const int warp = tid >> 5;                                                 \
    const int wm   = warp & 3;                                                 \
    const int wn   = warp >> 2;                                                \
    const int g    = lane >> 2;                                                \
    const int tq   = lane & 3;                                                 \
    const int a_row = wm * 32 + (lane & 15);                                   \
    const int a_kx  = (lane >> 4) * 16;                                        \
    const uint32_t aoffH0 = (uint32_t)(a_row * SA * 2 + a_kx);                 \
    const uint32_t aoffH1 = aoffH0 + 16 * SA * 2;                              \
    const int b_col = wn * 64 + (lane & 7) + ((lane >> 4) & 1) * 8;            \
    const int b_kx  = ((lane >> 3) & 1) * 16;                                  \
    const uint32_t boff0 = (uint32_t)(b_col * SA * 2 + b_kx)

#define ACC_INIT()                                                             \
    float acc[2][8][4];                                                        \
    _Pragma("unroll")                                                          \
    for (int mi = 0; mi < 2; mi++)                                             \
        _Pragma("unroll")                                                      \
        for (int ni = 0; ni < 8; ni++)                                         \
            _Pragma("unroll")                                                  \
            for (int j = 0; j < 4; j++) acc[mi][ni][j] = 0.0f

__device__ __forceinline__ void split1h(float v, __half& h, __half& l) {
    h = __float2half(v);
    l = __float2half(v - __half2float(h));
}
__device__ __forceinline__ float sigf(float x) { return 1.0f / (1.0f + __expf(-x)); }

// ---------------- init GEMM: h = xF @ WredF^T + bias -------------------------
__global__ void __launch_bounds__(256, 2)
gemm_init(const __half* __restrict__ AF, const __half* __restrict__ BF,
          const float* __restrict__ bias, float* __restrict__ C, int ldc)
{
    extern __shared__ char sm[];
    const uint32_t sb = (uint32_t)__cvta_generic_to_shared(sm);
    FRAG_SETUP();
    const int row0 = blockIdx.y * 128, col0 = blockIdx.x * 128;

    auto copy_stage = [&](int st, int kc) {
        const int k0 = kc * BK;
        char* d = sm + st * STG1P;
#pragma unroll
        for (int i = 0; i < 4; i++) {
            const int idx = i * 256 + tid;
            const int p = idx >> 9;
            const int rr = idx & 511;
            const int r = rr >> 2, j = rr & 3;
            const __half* src = p ? (BF + (size_t)(col0 + r) * KD + k0 + j * 8)
                                  : (AF + (size_t)(row0 + r) * KD + k0 + j * 8);
            cpasync16(d + p * PLANEB + r * (SA * 2) + j * 16, src);
        }
        asm volatile("cp.async.commit_group;" ::: "memory");
    };

    ACC_INIT();
    const int NC = KD / BK;
    copy_stage(0, 0);
    copy_stage(1, 1);
    for (int c = 0; c < NC; c++) {
        if (c + 1 < NC) asm volatile("cp.async.wait_group 1;" ::: "memory");
        else            asm volatile("cp.async.wait_group 0;" ::: "memory");
        __syncthreads();
        if (c + 2 < NC) copy_stage((c + 2) % 3, c + 2);
        GEMM1P(sb + (uint32_t)((c % 3) * STG1P));
    }
#pragma unroll
    for (int mi = 0; mi < 2; mi++) {
        const int r = row0 + wm * 32 + mi * 16 + g;
#pragma unroll
        for (int ni = 0; ni < 8; ni++) {
            const int cc = col0 + wn * 64 + ni * 8 + tq * 2;
            const float b0 = bias[cc], b1 = bias[cc + 1];
            *(float2*)(C + (size_t)r * ldc + cc) =
                make_float2(acc[mi][ni][0] + b0, acc[mi][ni][1] + b1);
            *(float2*)(C + (size_t)(r + 8) * ldc + cc) =
                make_float2(acc[mi][ni][2] + b0, acc[mi][ni][3] + b1);
        }
    }
}

// ---------------- Wfused GEMM (3-product fp16) -> single fp16 plane ----------
__global__ void __launch_bounds__(256, 2)
gemm_wfus(const __half* __restrict__ AH, const __half* __restrict__ AL,
          const __half* __restrict__ BHall, const __half* __restrict__ BLall,
          __half* __restrict__ fF)
{
    extern __shared__ char sm[];
    const uint32_t sb = (uint32_t)__cvta_generic_to_shared(sm);
    FRAG_SETUP();
    const int row0 = blockIdx.y * 128, col0 = blockIdx.x * 128;
    const int t = blockIdx.z;
    const __half* gp[4] = {AH, AL, BHall + (size_t)t * 65536,
                           BLall + (size_t)t * 65536};

    auto copy_stage = [&](int st, int kc) {
        const int k0 = kc * BK;
        char* dst0 = sm + st * STG4P;
#pragma unroll
        for (int i = 0; i < 8; i++) {
            const int idx = i * 256 + tid;
            const int p = idx >> 9, r = (idx >> 2) & 127, j = idx & 3;
            const int grow = ((p < 2) ? row0 : col0) + r;
            cpasync16(dst0 + p * PLANEB + r * (SA * 2) + j * 16,
                      gp[p] + (size_t)grow * 256 + k0 + j * 8);
        }
        asm volatile("cp.async.commit_group;" ::: "memory");
    };

    ACC_INIT();
    copy_stage(0, 0);
    for (int c = 0; c < 8; c++) {
        asm volatile("cp.async.wait_group 0;" ::: "memory");
        __syncthreads();
        if (c + 1 < 8) copy_stage((c + 1) & 1, c + 1);
        GEMM3P(sb + (c & 1) * STG4P);
    }
    const size_t tb = (size_t)t * 768 * KD;
#pragma unroll
    for (int mi = 0; mi < 2; mi++) {
        const int r = row0 + wm * 32 + mi * 16 + g;
#pragma unroll
        for (int ni = 0; ni < 8; ni++) {
            const int cc = col0 + wn * 64 + ni * 8 + tq * 2;
#pragma unroll
            for (int j = 0; j < 4; j++) {
                const int o  = (j < 2) ? r : r + 8;
                const int kk = cc + (j & 1);
                fF[tb + (size_t)o * KD + kk] = __float2half(acc[mi][ni][j]);
            }
        }
    }
}

// ---------------- step GEMM: gates(fp16) = [aggF|hF] @ B'^T + cbias ----------
__global__ void __launch_bounds__(256, 2)
gemm_step(const __half* __restrict__ aggF, const __half* __restrict__ hF,
          const __half* __restrict__ WfF, const __half* __restrict__ WhhF,
          const float* __restrict__ cbias, __half* __restrict__ C)
{
    extern __shared__ char sm[];
    const uint32_t sb = (uint32_t)__cvta_generic_to_shared(sm);
    FRAG_SETUP();
    const int bx   = blockIdx.x;
    const int row0 = blockIdx.y * 128, col0 = bx * 128;

    int kbeg, kend;
    if (bx < 4)      { kbeg = 0; kend = 16; }
    else if (bx < 6) { kbeg = 0; kend = 8;  }
    else             { kbeg = 8; kend = 16; }

    auto copy_stage = [&](int st, int kc) {
        const int k0 = kc * BK;
        const bool hi = k0 >= 256;
        const int ka = hi ? k0 - 256 : k0;
        const __half* aP = hi ? hF : aggF;
        char* d = sm + st * STG1P;
#pragma unroll
        for (int i = 0; i < 4; i++) {
            const int idx = i * 256 + tid;
            const int p = idx >> 9;
            const int rr = idx & 511;
            const int r = rr >> 2, j = rr & 3;
            const __half* src;
            if (p == 0) {
                src = aP + (size_t)(row0 + r) * KD + ka + j * 8;
            } else {
                const int c = col0 + r;
                if (hi) src = WhhF + (size_t)((c < 768) ? c : c - 256) * KD + ka + j * 8;
                else    src = WfF + (size_t)c * KD + ka + j * 8;
            }
            cpasync16(d + p * PLANEB + r * (SA * 2) + j * 16, src);
        }
        asm volatile("cp.async.commit_group;" ::: "memory");
    };

    ACC_INIT();
    copy_stage(0, kbeg);
    if (kbeg + 1 < kend) copy_stage(1, kbeg + 1);
    for (int c = kbeg; c < kend; c++) {
        if (c + 1 < kend) asm volatile("cp.async.wait_group 1;" ::: "memory");
        else              asm volatile("cp.async.wait_group 0;" ::: "memory");
        __syncthreads();
        if (c + 2 < kend) copy_stage((c + 2 - kbeg) % 3, c + 2);
        GEMM1P(sb + (uint32_t)(((c - kbeg) % 3) * STG1P));
    }
#pragma unroll
    for (int mi = 0; mi < 2; mi++) {
        const int r = row0 + wm * 32 + mi * 16 + g;
#pragma unroll
        for (int ni = 0; ni < 8; ni++) {
            const int cc = col0 + wn * 64 + ni * 8 + tq * 2;
            const float b0 = cbias[cc], b1 = cbias[cc + 1];
            *(__half2*)(C + (size_t)r * 1024 + cc) =
                __floats2half2_rn(acc[mi][ni][0] + b0, acc[mi][ni][1] + b1);
            *(__half2*)(C + (size_t)(r + 8) * 1024 + cc) =
                __floats2half2_rn(acc[mi][ni][2] + b0, acc[mi][ni][3] + b1);
        }
    }
}

// ---------------- prep kernels -----------------------------------------------
__global__ void prep_x(const float* __restrict__ x, __half* __restrict__ xf) {
    const int idx = blockIdx.x * 256 + threadIdx.x;
    if (idx >= NN * KD) return;
    const int row = idx >> 8, col = idx & 255;
    const float v = (row < NREAL && col < 200) ? x[row * 200 + col] : 0.0f;
    xf[idx] = __float2half(v);
}
__global__ void prep_wred(const float* __restrict__ W, __half* __restrict__ wf) {
    const int idx = blockIdx.x * 256 + threadIdx.x;
    if (idx >= 256 * KD) return;
    const int n = idx >> 8, k = idx & 255;
    const float v = (k < 200) ? W[n * 200 + k] : 0.0f;
    wf[idx] = __float2half(v);
}
__global__ void prep_single(const float* __restrict__ W, int n, __half* __restrict__ wf) {
    const int idx = blockIdx.x * 256 + threadIdx.x;
    if (idx >= n) return;
    wf[idx] = __float2half(W[idx]);
}
__global__ void prep_split(const float* __restrict__ W, int n,
                           __half* __restrict__ wh, __half* __restrict__ wl) {
    const int idx = blockIdx.x * 256 + threadIdx.x;
    if (idx >= n) return;
    split1h(W[idx], wh[idx], wl[idx]);
}
__global__ void prep_cbias(const float* __restrict__ bih, const float* __restrict__ bhh,
                           float* __restrict__ cb) {
    const int c = blockIdx.x * 256 + threadIdx.x;
    if (c >= 1024) return;
    float v;
    if (c < 512)       v = bih[c] + bhh[c];
    else if (c < 768)  v = bih[c];
    else               v = bhh[c - 256];
    cb[c] = v;
}
__global__ void split_h(const float* __restrict__ h, __half* __restrict__ hf) {
    const int idx = blockIdx.x * 256 + threadIdx.x;
    if (idx >= NN * HID) return;
    hf[idx] = __float2half(h[idx]);
}

// ---------------- CSR build (parallel 3-phase scan) --------------------------
__global__ void hist_kernel(const int* __restrict__ ei, int* __restrict__ cnt) {
    const int e = blockIdx.x * 256 + threadIdx.x;
    if (e >= NE) return;
    atomicAdd(&cnt[ei[NE + e]], 1);
}
__global__ void scan_local(const int* __restrict__ cnt, int* __restrict__ rowptr,
                           int* __restrict__ bsum) {
    __shared__ int s[1024];
    const int tid = threadIdx.x;
    const int idx = blockIdx.x * 1024 + tid;
    int v = (idx < NN) ? cnt[idx] : 0;
    s[tid] = v;
    __syncthreads();
#pragma unroll
    for (int off = 1; off < 1024; off <<= 1) {
        int t = (tid >= off) ? s[tid - off] : 0;
        __syncthreads();
        s[tid] += t;
        __syncthreads();
    }
    if (idx < NN) rowptr[idx + 1] = s[tid];
    if (tid == 1023) bsum[blockIdx.x] = s[1023];
}
__global__ void scan_bsum(const int* __restrict__ bsum, int* __restrict__ boff) {
    if (threadIdx.x == 0) {
        int acc = 0;
        for (int i = 0; i < SCANB; i++) { boff[i] = acc; acc += bsum[i]; }
    }
}
__global__ void scan_add(int* __restrict__ rowptr, const int* __restrict__ boff) {
    const int idx = blockIdx.x * 1024 + threadIdx.x;
    if (idx == 0) rowptr[0] = 0;
    if (idx < NN) rowptr[idx + 1] += boff[blockIdx.x];
}
__global__ void copycur_kernel(const int* __restrict__ rowptr, int* __restrict__ cur) {
    const int i = blockIdx.x * 256 + threadIdx.x;
    if (i < NN) cur[i] = rowptr[i];
}
__global__ void fill_kernel(const int* __restrict__ ei, int* __restrict__ cur,
                            int* __restrict__ eidx) {
    const int e = blockIdx.x * 256 + threadIdx.x;
    if (e >= NE) return;
    const int pos = atomicAdd(&cur[ei[NE + e]], 1);
    eidx[pos] = ei[e];
}

// ---------------- aggregation: warp/dst-node gather of hF -> fp16 plane ------
__global__ void agg_kernel(const __half* __restrict__ hF,
                           const int* __restrict__ rowptr, const int* __restrict__ eidx,
                           __half* __restrict__ aggF)
{
    const int w = (blockIdx.x * blockDim.x + threadIdx.x) >> 5;
    const int lane = threadIdx.x & 31;
    if (w >= NN) return;
    const int beg = rowptr[w], end = rowptr[w + 1];
    float a[8];
#pragma unroll
    for (int q = 0; q < 8; q++) a[q] = 0.0f;
    for (int i = beg; i < end; i++) {
        const int s = eidx[i];
        const uint4 v = *(const uint4*)(hF + (size_t)s * 256 + lane * 8);
        const __half2 h0 = *(const __half2*)&v.x;
        const __half2 h1 = *(const __half2*)&v.y;
        const __half2 h2 = *(const __half2*)&v.z;
        const __half2 h3 = *(const __half2*)&v.w;
        const float2 f0 = __half22float2(h0);
        const float2 f1 = __half22float2(h1);
        const float2 f2 = __half22float2(h2);
        const float2 f3 = __half22float2(h3);
        a[0] += f0.x; a[1] += f0.y; a[2] += f1.x; a[3] += f1.y;
        a[4] += f2.x; a[5] += f2.y; a[6] += f3.x; a[7] += f3.y;
    }
    __half2 p0 = __floats2half2_rn(a[0], a[1]);
    __half2 p1 = __floats2half2_rn(a[2], a[3]);
    __half2 p2 = __floats2half2_rn(a[4], a[5]);
    __half2 p3 = __floats2half2_rn(a[6], a[7]);
    uint4 v;
    v.x = *(unsigned*)&p0; v.y = *(unsigned*)&p1;
    v.z = *(unsigned*)&p2; v.w = *(unsigned*)&p3;
    *(uint4*)(aggF + (size_t)w * 256 + lane * 8) = v;
}

// ---------------- fused GRU (reads fp16 gates) -------------------------------
__global__ void gru_kernel(const __half* __restrict__ gates,
                           float* __restrict__ h, __half* __restrict__ hf)
{
    const int idx = blockIdx.x * blockDim.x + threadIdx.x;
    if (idx >= NN * 64) return;
    const int row = idx >> 6, c = (idx & 63) * 4;
    const __half* G = gates + (size_t)row * 1024;

    auto ld4 = [](const __half* p) {
        const uint2 u = *(const uint2*)p;
        const float2 f0 = __half22float2(*(const __half2*)&u.x);
        const float2 f1 = __half22float2(*(const __half2*)&u.y);
        return make_float4(f0.x, f0.y, f1.x, f1.y);
    };
    const float4 rs  = ld4(G + c);
    const float4 zs  = ld4(G + 256 + c);
    const float4 iv  = ld4(G + 512 + c);
    const float4 hv2 = ld4(G + 768 + c);
    float4* H = (float4*)(h + (size_t)row * 256 + c);
    const float4 hv = *H;

    float4 o;
    { float r = sigf(rs.x), z = sigf(zs.x);
      float n = tanhf(iv.x + r * hv2.x); o.x = (1.0f - z) * n + z * hv.x; }
    { float r = sigf(rs.y), z = sigf(zs.y);
      float n = tanhf(iv.y + r * hv2.y); o.y = (1.0f - z) * n + z * hv.y; }
    { float r = sigf(rs.z), z = sigf(zs.z);
      float n = tanhf(iv.z + r * hv2.z); o.z = (1.0f - z) * n + z * hv.z; }
    { float r = sigf(rs.w), z = sigf(zs.w);
      float n = tanhf(iv.w + r * hv2.w); o.w = (1.0f - z) * n + z * hv.w; }
    *H = o;

    __half2 p01 = __floats2half2_rn(o.x, o.y);
    __half2 p23 = __floats2half2_rn(o.z, o.w);
    uint2 v;
    v.x = *(unsigned*)&p01; v.y = *(unsigned*)&p23;
    *(uint2*)(hf + (size_t)row * 256 + c) = v;
}

// ---------------- head -------------------------------------------------------
__global__ void head_kernel(const float* __restrict__ h,
                            const float* __restrict__ W_lin,
                            const float* __restrict__ b_lin,
                            float* __restrict__ out, int N)
{
    const int gt = blockIdx.x * blockDim.x + threadIdx.x;
    const int node = gt >> 5;
    const int lane = gt & 31;
    if (node >= N) return;
    const float4* hr = (const float4*)(h + (size_t)node * HID);
    const float4* w0 = (const float4*)(W_lin);
    const float4* w1 = (const float4*)(W_lin + HID);
    float a0 = 0.0f, a1 = 0.0f;
#pragma unroll
    for (int it = 0; it < 2; it++) {
        const int i = lane + it * 32;
        float4 v = hr[i];
        v.x = fmaxf(v.x, 0.f); v.y = fmaxf(v.y, 0.f);
        v.z = fmaxf(v.z, 0.f); v.w = fmaxf(v.w, 0.f);
        const float4 x0 = w0[i], x1 = w1[i];
        a0 += v.x * x0.x + v.y * x0.y + v.z * x0.z + v.w * x0.w;
        a1 += v.x * x1.x + v.y * x1.y + v.z * x1.z + v.w * x1.w;
    }
#pragma unroll
    for (int off = 16; off > 0; off >>= 1) {
        a0 += __shfl_down_sync(0xffffffffu, a0, off);
        a1 += __shfl_down_sync(0xffffffffu, a1, off);
    }
    if (lane == 0) {
        const float o0 = a0 + b_lin[0];
        const float o1 = a1 + b_lin[1];
        const float mx = fmaxf(o0, o1);
        const float lse = mx + logf(expf(o0 - mx) + expf(o1 - mx));
        out[(size_t)node * 2 + 0] = o0 - lse;
        out[(size_t)node * 2 + 1] = o1 - lse;
    }
}

// ---------------- launch -----------------------------------------------------
extern "C" void kernel_launch(void* const* d_in, const int* in_sizes, int n_in,
                              void* d_out, int out_size)
{
    const float* x        = (const float*)d_in[0];
    const int*   ei       = (const int*)  d_in[1];
    const float* W_reduce = (const float*)d_in[3];
    const float* b_reduce = (const float*)d_in[4];
    const float* W_ggc    = (const float*)d_in[5];
    const float* W_ih     = (const float*)d_in[6];
    const float* W_hh     = (const float*)d_in[7];
    const float* b_ih     = (const float*)d_in[8];
    const float* b_hh     = (const float*)d_in[9];
    const float* W_lin    = (const float*)d_in[10];
    const float* b_lin    = (const float*)d_in[11];
    float* out = (float*)d_out;

    float *h, *cbias;
    __half *gates, *hF, *xF, *aggF, *WfF, *WhhF, *WrF, *WiH, *WiL, *WgH, *WgL;
    int *cnt, *rowptr, *cur, *eidx, *bsum, *boff;
    cudaGetSymbolAddress((void**)&h, g_h);
    cudaGetSymbolAddress((void**)&gates, g_gates);
    cudaGetSymbolAddress((void**)&cbias, g_cbias);
    cudaGetSymbolAddress((void**)&hF, g_hF);
    cudaGetSymbolAddress((void**)&xF, g_xF);
    cudaGetSymbolAddress((void**)&aggF, g_aggF);
    cudaGetSymbolAddress((void**)&WfF, g_WfusF);
    cudaGetSymbolAddress((void**)&WhhF, g_WhhF);
    cudaGetSymbolAddress((void**)&WrF, g_WredF);
    cudaGetSymbolAddress((void**)&WiH, g_WihH);
    cudaGetSymbolAddress((void**)&WiL, g_WihL);
    cudaGetSymbolAddress((void**)&WgH, g_WgH);
    cudaGetSymbolAddress((void**)&WgL, g_WgL);
    cudaGetSymbolAddress((void**)&cnt, g_cnt);
    cudaGetSymbolAddress((void**)&rowptr, g_rowptr);
    cudaGetSymbolAddress((void**)&cur, g_cur);
    cudaGetSymbolAddress((void**)&eidx, g_eidx);
    cudaGetSymbolAddress((void**)&bsum, g_bsum);
    cudaGetSymbolAddress((void**)&boff, g_boff);

    cudaFuncSetAttribute(gemm_init, cudaFuncAttributeMaxDynamicSharedMemorySize, GSMEM1);
    cudaFuncSetAttribute(gemm_step, cudaFuncAttributeMaxDynamicSharedMemorySize, GSMEM1);
    cudaFuncSetAttribute(gemm_wfus, cudaFuncAttributeMaxDynamicSharedMemorySize, GSMEM4);

    // ---- preprocessing ----
    prep_x<<<(NN * KD + 255) / 256, 256>>>(x, xF);
    prep_wred<<<(256 * KD + 255) / 256, 256>>>(W_reduce, WrF);
    prep_single<<<(768 * KD + 255) / 256, 256>>>(W_hh, 768 * KD, WhhF);
    prep_split<<<(768 * KD + 255) / 256, 256>>>(W_ih, 768 * KD, WiH, WiL);
    prep_split<<<(NSTEP * 65536 + 255) / 256, 256>>>(W_ggc, NSTEP * 65536, WgH, WgL);
    gemm_wfus<<<dim3(2, 6, NSTEP), 256, GSMEM4>>>(WiH, WiL, WgH, WgL, WfF);
    prep_cbias<<<4, 256>>>(b_ih, b_hh, cbias);
    cudaMemsetAsync(cnt, 0, NN * sizeof(int));
    hist_kernel<<<(NE + 255) / 256, 256>>>(ei, cnt);
    scan_local<<<SCANB, 1024>>>(cnt, rowptr, bsum);
    scan_bsum<<<1, 32>>>(bsum, boff);
    scan_add<<<SCANB, 1024>>>(rowptr, boff);
    copycur_kernel<<<(NN + 255) / 256, 256>>>(rowptr, cur);
    fill_kernel<<<(NE + 255) / 256, 256>>>(ei, cur, eidx);

    const int MB = NN / 128;   // 391

    // h = x @ W_reduce^T + b_reduce
    gemm_init<<<dim3(2, MB), 256, GSMEM1>>>(xF, WrF, b_reduce, h, 256);
    split_h<<<(NN * HID + 255) / 256, 256>>>(h, hF);

    for (int t = 0; t < NSTEP; t++) {
        agg_kernel<<<(NN * 32 + 255) / 256, 256>>>(hF, rowptr, eidx, aggF);
        gemm_step<<<dim3(8, MB), 256, GSMEM1>>>(
            aggF, hF, WfF + (size_t)t * 768 * KD, WhhF, cbias, gates);
        gru_kernel<<<(NN * 64 + 255) / 256, 256>>>(gates, h, hF);
    }

    head_kernel<<<(NREAL * 32 + 255) / 256, 256>>>(h, W_lin, b_lin, out, NREAL);
}